// round 1
// baseline (speedup 1.0000x reference)
#include <cuda_runtime.h>
#include <math.h>

#define VNUM   5023
#define NJ     5
#define NB     1024
#define NSHAPE 100
#define NEXPR  50
#define NBETA  150
#define NLMK   68
#define NPOSE  36          // (NJ-1)*9
#define JR_COLS 453        // 450 shapedir cols + 3 v_template cols
#define NCHUNK 64
#define CHUNK_V 79         // ceil(5023/64)

// ---- device scratch (no allocations allowed) ----
__device__ float g_partial[NCHUNK * NJ * JR_COLS];   // ~580 KB
__device__ float g_Jr[NJ * JR_COLS];                 // folded J regressor
__device__ float g_pf[NB * NPOSE];                   // pose features
__device__ float g_relT[NB * NJ * 12];               // rel transforms (3x4 row-major)

// ============================================================
// Kernel A: partial sums of Jreg @ [shapedirs | v_template]
// grid = NCHUNK blocks, 256 threads. Coalesced over columns.
// ============================================================
__global__ void kernA(const float* __restrict__ sd, const float* __restrict__ vt,
                      const float* __restrict__ Jreg)
{
    __shared__ float s_jr[NJ * CHUNK_V];
    int chunk = blockIdx.x;
    int v0 = chunk * CHUNK_V;
    int nv = VNUM - v0; if (nv > CHUNK_V) nv = CHUNK_V; if (nv < 0) nv = 0;

    for (int i = threadIdx.x; i < NJ * CHUNK_V; i += blockDim.x) {
        int j = i / CHUNK_V, vv = i % CHUNK_V;
        s_jr[i] = (vv < nv) ? Jreg[j * VNUM + v0 + vv] : 0.f;
    }
    __syncthreads();

    int col0 = threadIdx.x;         // 0..255  (< 453 always)
    int col1 = threadIdx.x + 256;   // may be >= 453
    float acc0[NJ], acc1[NJ];
#pragma unroll
    for (int j = 0; j < NJ; j++) { acc0[j] = 0.f; acc1[j] = 0.f; }

    for (int vv = 0; vv < nv; vv++) {
        int v = v0 + vv;
        float x0 = (col0 < 450) ? sd[v * 450 + col0] : vt[v * 3 + (col0 - 450)];
#pragma unroll
        for (int j = 0; j < NJ; j++) acc0[j] = fmaf(s_jr[j * CHUNK_V + vv], x0, acc0[j]);
        if (col1 < JR_COLS) {
            float x1 = (col1 < 450) ? sd[v * 450 + col1] : vt[v * 3 + (col1 - 450)];
#pragma unroll
            for (int j = 0; j < NJ; j++) acc1[j] = fmaf(s_jr[j * CHUNK_V + vv], x1, acc1[j]);
        }
    }
#pragma unroll
    for (int j = 0; j < NJ; j++) {
        g_partial[(chunk * NJ + j) * JR_COLS + col0] = acc0[j];
        if (col1 < JR_COLS) g_partial[(chunk * NJ + j) * JR_COLS + col1] = acc1[j];
    }
}

// ============================================================
// Kernel A2: reduce partials -> g_Jr
// ============================================================
__global__ void kernA2()
{
    int j = blockIdx.x;
    int col = threadIdx.x;
    if (col >= JR_COLS) return;
    float s = 0.f;
    for (int ch = 0; ch < NCHUNK; ch++) s += g_partial[(ch * NJ + j) * JR_COLS + col];
    g_Jr[j * JR_COLS + col] = s;
}

// ============================================================
// Kernel B: per-batch joints, Rodrigues, kinematic chain
// -> g_pf (B x 36), g_relT (B x 5 x 12)
// ============================================================
__global__ void kernB(const float* __restrict__ shape, const float* __restrict__ expr,
                      const float* __restrict__ pose, const float* __restrict__ eye,
                      const float* __restrict__ neck)
{
    __shared__ float s_jr[NJ * JR_COLS];
    for (int i = threadIdx.x; i < NJ * JR_COLS; i += blockDim.x) s_jr[i] = g_Jr[i];
    __syncthreads();

    int b = blockIdx.x * blockDim.x + threadIdx.x;
    if (b >= NB) return;

    // joints J[j][c] = Jr_vt + Jr_sd @ beta
    float J[NJ][3];
#pragma unroll
    for (int j = 0; j < NJ; j++)
#pragma unroll
        for (int c = 0; c < 3; c++) J[j][c] = s_jr[j * JR_COLS + 450 + c];

    for (int l = 0; l < NBETA; l++) {
        float bl = (l < NSHAPE) ? shape[b * NSHAPE + l] : expr[b * NEXPR + l - NSHAPE];
#pragma unroll
        for (int j = 0; j < NJ; j++)
#pragma unroll
            for (int c = 0; c < 3; c++) J[j][c] = fmaf(s_jr[j * JR_COLS + l], bl, J[j][c]);
    }

    // full_pose = [pose[:3], neck, pose[3:6], eye(6)]
    float fp[15];
    fp[0] = pose[b * 6 + 0]; fp[1] = pose[b * 6 + 1]; fp[2] = pose[b * 6 + 2];
    fp[3] = neck[0]; fp[4] = neck[1]; fp[5] = neck[2];
    fp[6] = pose[b * 6 + 3]; fp[7] = pose[b * 6 + 4]; fp[8] = pose[b * 6 + 5];
#pragma unroll
    for (int k = 0; k < 6; k++) fp[9 + k] = eye[k];

    // Rodrigues (matching reference: angle uses rot_vec + 1e-8 elementwise)
    float R[NJ][9];
#pragma unroll
    for (int j = 0; j < NJ; j++) {
        float x = fp[j * 3 + 0], y = fp[j * 3 + 1], z = fp[j * 3 + 2];
        float xa = x + 1e-8f, ya = y + 1e-8f, za = z + 1e-8f;
        float ang = sqrtf(xa * xa + ya * ya + za * za);
        float inv = 1.f / ang;
        float rx = x * inv, ry = y * inv, rz = z * inv;
        float s, c;
        sincosf(ang, &s, &c);
        float t = 1.f - c;
        R[j][0] = 1.f - t * (ry * ry + rz * rz);
        R[j][1] = -s * rz + t * rx * ry;
        R[j][2] =  s * ry + t * rx * rz;
        R[j][3] =  s * rz + t * rx * ry;
        R[j][4] = 1.f - t * (rx * rx + rz * rz);
        R[j][5] = -s * rx + t * ry * rz;
        R[j][6] = -s * ry + t * rx * rz;
        R[j][7] =  s * rx + t * ry * rz;
        R[j][8] = 1.f - t * (rx * rx + ry * ry);
    }

    // pose feature
#pragma unroll
    for (int j = 1; j < NJ; j++)
#pragma unroll
        for (int k = 0; k < 9; k++) {
            float d = (k == 0 || k == 4 || k == 8) ? 1.f : 0.f;
            g_pf[b * NPOSE + (j - 1) * 9 + k] = R[j][k] - d;
        }

    // relative joints (parents = [-1,0,1,1,1])
    const int par[NJ] = { -1, 0, 1, 1, 1 };
    float rel[NJ][3];
#pragma unroll
    for (int c = 0; c < 3; c++) rel[0][c] = J[0][c];
#pragma unroll
    for (int j = 1; j < NJ; j++)
#pragma unroll
        for (int c = 0; c < 3; c++) rel[j][c] = J[j][c] - J[par[j]][c];

    // kinematic chain
    float cR[NJ][9], ct[NJ][3];
#pragma unroll
    for (int k = 0; k < 9; k++) cR[0][k] = R[0][k];
#pragma unroll
    for (int c = 0; c < 3; c++) ct[0][c] = rel[0][c];
#pragma unroll
    for (int j = 1; j < NJ; j++) {
        int p = par[j];
#pragma unroll
        for (int r = 0; r < 3; r++) {
#pragma unroll
            for (int c = 0; c < 3; c++)
                cR[j][r * 3 + c] = cR[p][r * 3 + 0] * R[j][0 + c]
                                 + cR[p][r * 3 + 1] * R[j][3 + c]
                                 + cR[p][r * 3 + 2] * R[j][6 + c];
            ct[j][r] = cR[p][r * 3 + 0] * rel[j][0] + cR[p][r * 3 + 1] * rel[j][1]
                     + cR[p][r * 3 + 2] * rel[j][2] + ct[p][r];
        }
    }

    // rel transforms: t' = t - R_chain @ J
#pragma unroll
    for (int j = 0; j < NJ; j++)
#pragma unroll
        for (int r = 0; r < 3; r++) {
            float tr = ct[j][r] - (cR[j][r * 3 + 0] * J[j][0] + cR[j][r * 3 + 1] * J[j][1]
                                 + cR[j][r * 3 + 2] * J[j][2]);
            g_relT[b * 60 + j * 12 + r * 4 + 0] = cR[j][r * 3 + 0];
            g_relT[b * 60 + j * 12 + r * 4 + 1] = cR[j][r * 3 + 1];
            g_relT[b * 60 + j * 12 + r * 4 + 2] = cR[j][r * 3 + 2];
            g_relT[b * 60 + j * 12 + r * 4 + 3] = tr;
        }
}

// ============================================================
// Kernel C: fused blendshape GEMM + pose-corrective + LBS skinning
// Tile: 32 batches x 32 vertices per 256-thread CTA; each thread: 4 b x 1 v.
// ============================================================
#define TILE_V 32
#define TILE_B 32
#define SD_PITCH 460       // 115 float4 chunks (odd) -> conflict-free LDS.128
#define C_PITCH 152        // per-component pitch within an sd row (150 + 2 pad)
#define BETA_PITCH 152
#define PD_PITCH 100

#define OFF_BETA (TILE_V * SD_PITCH)               // 14720
#define OFF_PD   (OFF_BETA + TILE_B * BETA_PITCH)  // +4864 = 19584
#define OFF_PF   (OFF_PD + NPOSE * PD_PITCH)       // +3600 = 23184
#define OFF_T    (OFF_PF + TILE_B * NPOSE)         // +1152 = 24336
#define SMEM_FLOATS (OFF_T + TILE_B * 60)          // +1920 = 26256  (~105 KB)

__global__ void __launch_bounds__(256, 2) kernC(
    const float* __restrict__ shape, const float* __restrict__ expr,
    const float* __restrict__ vt, const float* __restrict__ sd,
    const float* __restrict__ pd, const float* __restrict__ lw,
    float* __restrict__ out)
{
    extern __shared__ float sm[];
    float* s_sd   = sm;
    float* s_beta = sm + OFF_BETA;
    float* s_pd   = sm + OFF_PD;
    float* s_pf   = sm + OFF_PF;
    float* s_T    = sm + OFF_T;

    int v0 = blockIdx.x * TILE_V;
    int b0 = blockIdx.y * TILE_B;
    int tid = threadIdx.x;

    // --- stage shapedirs tile (reorder to [v][c*152 + l]) ---
    for (int i = tid; i < TILE_V * 450; i += 256) {
        int vl = i / 450, j = i % 450;
        int c = j / 150, l = j % 150;
        int v = min(v0 + vl, VNUM - 1);
        s_sd[vl * SD_PITCH + c * C_PITCH + l] = sd[v * 450 + j];
    }
    // zero K-pad (l = 150,151)
    for (int i = tid; i < TILE_V * 6; i += 256) {
        int vl = i / 6, r = i % 6;
        s_sd[vl * SD_PITCH + (r >> 1) * C_PITCH + 150 + (r & 1)] = 0.f;
    }
    // --- stage betas (concat shape|expr, zero-padded to 152) ---
    for (int i = tid; i < TILE_B * BETA_PITCH; i += 256) {
        int bl = i / BETA_PITCH, l = i % BETA_PITCH;
        int b = b0 + bl;
        float x = 0.f;
        if (l < NSHAPE)      x = shape[b * NSHAPE + l];
        else if (l < NBETA)  x = expr[b * NEXPR + l - NSHAPE];
        s_beta[i] = x;
    }
    // --- stage posedirs tile ---
    for (int i = tid; i < NPOSE * 96; i += 256) {
        int p = i / 96, k = i % 96;
        int vc = v0 * 3 + k;
        s_pd[p * PD_PITCH + k] = (vc < VNUM * 3) ? pd[p * (VNUM * 3) + vc] : 0.f;
    }
    // --- stage pose features / rel transforms ---
    for (int i = tid; i < TILE_B * NPOSE; i += 256) s_pf[i] = g_pf[b0 * NPOSE + i];
    for (int i = tid; i < TILE_B * 60;    i += 256) s_T[i]  = g_relT[b0 * 60 + i];
    __syncthreads();

    int vl = tid & 31;              // lane = vertex -> sd reads conflict-free
    int bq = (tid >> 5) * 4;        // warp shares batch quad -> beta reads broadcast
    int v = v0 + vl;
    int vc = min(v, VNUM - 1);

    float acc[4][3];
    {
        float t0 = vt[vc * 3 + 0], t1 = vt[vc * 3 + 1], t2 = vt[vc * 3 + 2];
#pragma unroll
        for (int bi = 0; bi < 4; bi++) { acc[bi][0] = t0; acc[bi][1] = t1; acc[bi][2] = t2; }
    }

    const float4* a0p = (const float4*)(s_sd + vl * SD_PITCH + 0 * C_PITCH);
    const float4* a1p = (const float4*)(s_sd + vl * SD_PITCH + 1 * C_PITCH);
    const float4* a2p = (const float4*)(s_sd + vl * SD_PITCH + 2 * C_PITCH);
    const float4* w0p = (const float4*)(s_beta + (bq + 0) * BETA_PITCH);
    const float4* w1p = (const float4*)(s_beta + (bq + 1) * BETA_PITCH);
    const float4* w2p = (const float4*)(s_beta + (bq + 2) * BETA_PITCH);
    const float4* w3p = (const float4*)(s_beta + (bq + 3) * BETA_PITCH);

#pragma unroll 2
    for (int ch = 0; ch < BETA_PITCH / 4; ch++) {   // 38 chunks of 4 K-values
        float4 a0 = a0p[ch], a1 = a1p[ch], a2 = a2p[ch];
        float4 w0 = w0p[ch], w1 = w1p[ch], w2 = w2p[ch], w3 = w3p[ch];
#define STEP(bi, W)                                                                    \
        acc[bi][0] = fmaf(a0.x, W.x, fmaf(a0.y, W.y, fmaf(a0.z, W.z, fmaf(a0.w, W.w, acc[bi][0])))); \
        acc[bi][1] = fmaf(a1.x, W.x, fmaf(a1.y, W.y, fmaf(a1.z, W.z, fmaf(a1.w, W.w, acc[bi][1])))); \
        acc[bi][2] = fmaf(a2.x, W.x, fmaf(a2.y, W.y, fmaf(a2.z, W.z, fmaf(a2.w, W.w, acc[bi][2]))));
        STEP(0, w0) STEP(1, w1) STEP(2, w2) STEP(3, w3)
#undef STEP
    }

    // pose correctives
#pragma unroll 4
    for (int p = 0; p < NPOSE; p++) {
        float d0 = s_pd[p * PD_PITCH + vl * 3 + 0];
        float d1 = s_pd[p * PD_PITCH + vl * 3 + 1];
        float d2 = s_pd[p * PD_PITCH + vl * 3 + 2];
#pragma unroll
        for (int bi = 0; bi < 4; bi++) {
            float f = s_pf[(bq + bi) * NPOSE + p];
            acc[bi][0] = fmaf(f, d0, acc[bi][0]);
            acc[bi][1] = fmaf(f, d1, acc[bi][1]);
            acc[bi][2] = fmaf(f, d2, acc[bi][2]);
        }
    }

    // LBS blend + transform
    float w[NJ];
#pragma unroll
    for (int j = 0; j < NJ; j++) w[j] = lw[vc * NJ + j];
    bool ok = (v < VNUM);

#pragma unroll
    for (int bi = 0; bi < 4; bi++) {
        int bl = bq + bi;
        float T[12];
#pragma unroll
        for (int k = 0; k < 12; k++) {
            float s = 0.f;
#pragma unroll
            for (int j = 0; j < NJ; j++) s = fmaf(w[j], s_T[bl * 60 + j * 12 + k], s);
            T[k] = s;
        }
        float px = acc[bi][0], py = acc[bi][1], pz = acc[bi][2];
        float ox = fmaf(T[0], px, fmaf(T[1],  py, fmaf(T[2],  pz, T[3])));
        float oy = fmaf(T[4], px, fmaf(T[5],  py, fmaf(T[6],  pz, T[7])));
        float oz = fmaf(T[8], px, fmaf(T[9],  py, fmaf(T[10], pz, T[11])));
        if (ok) {
            size_t base = ((size_t)(b0 + bl) * VNUM + v) * 3;
            out[base + 0] = ox; out[base + 1] = oy; out[base + 2] = oz;
        }
    }
}

// ============================================================
// Kernel D: landmark gather
// ============================================================
__global__ void kernD(const int* __restrict__ land, const float* __restrict__ verts,
                      float* __restrict__ lmk)
{
    int i = blockIdx.x * blockDim.x + threadIdx.x;
    if (i >= NB * NLMK) return;
    int b = i / NLMK, k = i % NLMK;
    int v = land[k];
    size_t src = ((size_t)b * VNUM + v) * 3;
    size_t dst = (size_t)i * 3;
    lmk[dst + 0] = verts[src + 0];
    lmk[dst + 1] = verts[src + 1];
    lmk[dst + 2] = verts[src + 2];
}

// ============================================================
extern "C" void kernel_launch(void* const* d_in, const int* in_sizes, int n_in,
                              void* d_out, int out_size)
{
    const float* shape = (const float*)d_in[0];
    const float* expr  = (const float*)d_in[1];
    const float* pose  = (const float*)d_in[2];
    const int*   land  = (const int*)  d_in[3];
    const float* vt    = (const float*)d_in[4];
    const float* sd    = (const float*)d_in[5];
    const float* pd    = (const float*)d_in[6];
    const float* Jreg  = (const float*)d_in[7];
    const float* lw    = (const float*)d_in[8];
    const float* eye   = (const float*)d_in[9];
    const float* neck  = (const float*)d_in[10];
    float* out = (float*)d_out;

    cudaFuncSetAttribute(kernC, cudaFuncAttributeMaxDynamicSharedMemorySize,
                         SMEM_FLOATS * (int)sizeof(float));

    kernA<<<NCHUNK, 256>>>(sd, vt, Jreg);
    kernA2<<<NJ, 512>>>();
    kernB<<<NB / 128, 128>>>(shape, expr, pose, eye, neck);

    dim3 g((VNUM + TILE_V - 1) / TILE_V, NB / TILE_B);
    kernC<<<g, 256, SMEM_FLOATS * (int)sizeof(float)>>>(shape, expr, vt, sd, pd, lw, out);

    float* lmk = out + (size_t)NB * VNUM * 3;
    kernD<<<(NB * NLMK + 255) / 256, 256>>>(land, out, lmk);
}

// round 3
// speedup vs baseline: 2.5111x; 2.5111x over previous
#include <cuda_runtime.h>
#include <cuda_bf16.h>
#include <math.h>
#include <stdint.h>

#define VNUM   5023
#define NJ     5
#define NB     1024
#define NSHAPE 100
#define NEXPR  50
#define NBETA  150
#define NLMK   68
#define NPOSE  36
#define JR_COLS 453
#define NCHUNK 64
#define CHUNK_V 79
#define PD_N   (VNUM * 3)      // 15069

#define KP    192              // padded K: 150 betas + 36 pose feats + 6 zero
#define NPAD4 20096            // 157 * 128 >= 4*VNUM = 20092

// ---- device scratch ----
__device__ float g_partial[NCHUNK * NJ * JR_COLS];
__device__ float g_Jr[NJ * JR_COLS];
__device__ float g_pf[NB * NPOSE];
__device__ float g_relT[NB * NJ * 12];
__device__ float g_pdT[PD_N * 36];                    // transposed posedirs, 2.2 MB
__device__ __nv_bfloat16 g_A[NB * KP];                // 0.4 MB
__device__ __nv_bfloat16 g_B4[(size_t)NPAD4 * KP];    // 7.7 MB

__device__ __forceinline__ uint32_t smem_u32(const void* p) {
    uint32_t a;
    asm("{ .reg .u64 t; cvta.to.shared.u64 t, %1; cvt.u32.u64 %0, t; }" : "=r"(a) : "l"(p));
    return a;
}

#define LDSM4(R0, R1, R2, R3, ADDR) \
    asm volatile("ldmatrix.sync.aligned.m8n8.x4.shared.b16 {%0,%1,%2,%3}, [%4];" \
        : "=r"(R0), "=r"(R1), "=r"(R2), "=r"(R3) : "r"(ADDR))

#define MMA16816(C, A0, A1, A2, A3, B0, B1) \
    asm volatile("mma.sync.aligned.m16n8k16.row.col.f32.bf16.bf16.f32 " \
        "{%0,%1,%2,%3},{%4,%5,%6,%7},{%8,%9},{%0,%1,%2,%3};" \
        : "+f"((C)[0]), "+f"((C)[1]), "+f"((C)[2]), "+f"((C)[3]) \
        : "r"(A0), "r"(A1), "r"(A2), "r"(A3), "r"(B0), "r"(B1))

// ============================================================
// Kernel A: partial sums of Jreg @ [shapedirs | v_template]
// ============================================================
__global__ void kernA(const float* __restrict__ sd, const float* __restrict__ vt,
                      const float* __restrict__ Jreg)
{
    __shared__ float s_jr[NJ * CHUNK_V];
    int chunk = blockIdx.x;
    int v0 = chunk * CHUNK_V;
    int nv = VNUM - v0; if (nv > CHUNK_V) nv = CHUNK_V; if (nv < 0) nv = 0;

    for (int i = threadIdx.x; i < NJ * CHUNK_V; i += blockDim.x) {
        int j = i / CHUNK_V, vv = i % CHUNK_V;
        s_jr[i] = (vv < nv) ? Jreg[j * VNUM + v0 + vv] : 0.f;
    }
    __syncthreads();

    int col0 = threadIdx.x;
    int col1 = threadIdx.x + 256;
    float acc0[NJ], acc1[NJ];
#pragma unroll
    for (int j = 0; j < NJ; j++) { acc0[j] = 0.f; acc1[j] = 0.f; }

    for (int vv = 0; vv < nv; vv++) {
        int v = v0 + vv;
        float x0 = (col0 < 450) ? sd[v * 450 + col0] : vt[v * 3 + (col0 - 450)];
#pragma unroll
        for (int j = 0; j < NJ; j++) acc0[j] = fmaf(s_jr[j * CHUNK_V + vv], x0, acc0[j]);
        if (col1 < JR_COLS) {
            float x1 = (col1 < 450) ? sd[v * 450 + col1] : vt[v * 3 + (col1 - 450)];
#pragma unroll
            for (int j = 0; j < NJ; j++) acc1[j] = fmaf(s_jr[j * CHUNK_V + vv], x1, acc1[j]);
        }
    }
#pragma unroll
    for (int j = 0; j < NJ; j++) {
        g_partial[(chunk * NJ + j) * JR_COLS + col0] = acc0[j];
        if (col1 < JR_COLS) g_partial[(chunk * NJ + j) * JR_COLS + col1] = acc1[j];
    }
}

__global__ void kernA2()
{
    int j = blockIdx.x;
    int col = threadIdx.x;
    if (col >= JR_COLS) return;
    float s = 0.f;
    for (int ch = 0; ch < NCHUNK; ch++) s += g_partial[(ch * NJ + j) * JR_COLS + col];
    g_Jr[j * JR_COLS + col] = s;
}

// ============================================================
// Kernel B: per-batch joints, Rodrigues, kinematic chain
// ============================================================
__global__ void kernB(const float* __restrict__ shape, const float* __restrict__ expr,
                      const float* __restrict__ pose, const float* __restrict__ eye,
                      const float* __restrict__ neck)
{
    __shared__ float s_jr[NJ * JR_COLS];
    for (int i = threadIdx.x; i < NJ * JR_COLS; i += blockDim.x) s_jr[i] = g_Jr[i];
    __syncthreads();

    int b = blockIdx.x * blockDim.x + threadIdx.x;
    if (b >= NB) return;

    float J[NJ][3];
#pragma unroll
    for (int j = 0; j < NJ; j++)
#pragma unroll
        for (int c = 0; c < 3; c++) J[j][c] = s_jr[j * JR_COLS + 450 + c];

    for (int l = 0; l < NBETA; l++) {
        float bl = (l < NSHAPE) ? shape[b * NSHAPE + l] : expr[b * NEXPR + l - NSHAPE];
#pragma unroll
        for (int j = 0; j < NJ; j++)
#pragma unroll
            for (int c = 0; c < 3; c++) J[j][c] = fmaf(s_jr[j * JR_COLS + l], bl, J[j][c]);
    }

    float fp[15];
    fp[0] = pose[b * 6 + 0]; fp[1] = pose[b * 6 + 1]; fp[2] = pose[b * 6 + 2];
    fp[3] = neck[0]; fp[4] = neck[1]; fp[5] = neck[2];
    fp[6] = pose[b * 6 + 3]; fp[7] = pose[b * 6 + 4]; fp[8] = pose[b * 6 + 5];
#pragma unroll
    for (int k = 0; k < 6; k++) fp[9 + k] = eye[k];

    float R[NJ][9];
#pragma unroll
    for (int j = 0; j < NJ; j++) {
        float x = fp[j * 3 + 0], y = fp[j * 3 + 1], z = fp[j * 3 + 2];
        float xa = x + 1e-8f, ya = y + 1e-8f, za = z + 1e-8f;
        float ang = sqrtf(xa * xa + ya * ya + za * za);
        float inv = 1.f / ang;
        float rx = x * inv, ry = y * inv, rz = z * inv;
        float s, c;
        sincosf(ang, &s, &c);
        float t = 1.f - c;
        R[j][0] = 1.f - t * (ry * ry + rz * rz);
        R[j][1] = -s * rz + t * rx * ry;
        R[j][2] =  s * ry + t * rx * rz;
        R[j][3] =  s * rz + t * rx * ry;
        R[j][4] = 1.f - t * (rx * rx + rz * rz);
        R[j][5] = -s * rx + t * ry * rz;
        R[j][6] = -s * ry + t * rx * rz;
        R[j][7] =  s * rx + t * ry * rz;
        R[j][8] = 1.f - t * (rx * rx + ry * ry);
    }

#pragma unroll
    for (int j = 1; j < NJ; j++)
#pragma unroll
        for (int k = 0; k < 9; k++) {
            float d = (k == 0 || k == 4 || k == 8) ? 1.f : 0.f;
            g_pf[b * NPOSE + (j - 1) * 9 + k] = R[j][k] - d;
        }

    const int par[NJ] = { -1, 0, 1, 1, 1 };
    float rel[NJ][3];
#pragma unroll
    for (int c = 0; c < 3; c++) rel[0][c] = J[0][c];
#pragma unroll
    for (int j = 1; j < NJ; j++)
#pragma unroll
        for (int c = 0; c < 3; c++) rel[j][c] = J[j][c] - J[par[j]][c];

    float cR[NJ][9], ct[NJ][3];
#pragma unroll
    for (int k = 0; k < 9; k++) cR[0][k] = R[0][k];
#pragma unroll
    for (int c = 0; c < 3; c++) ct[0][c] = rel[0][c];
#pragma unroll
    for (int j = 1; j < NJ; j++) {
        int p = par[j];
#pragma unroll
        for (int r = 0; r < 3; r++) {
#pragma unroll
            for (int c = 0; c < 3; c++)
                cR[j][r * 3 + c] = cR[p][r * 3 + 0] * R[j][0 + c]
                                 + cR[p][r * 3 + 1] * R[j][3 + c]
                                 + cR[p][r * 3 + 2] * R[j][6 + c];
            ct[j][r] = cR[p][r * 3 + 0] * rel[j][0] + cR[p][r * 3 + 1] * rel[j][1]
                     + cR[p][r * 3 + 2] * rel[j][2] + ct[p][r];
        }
    }

#pragma unroll
    for (int j = 0; j < NJ; j++)
#pragma unroll
        for (int r = 0; r < 3; r++) {
            float tr = ct[j][r] - (cR[j][r * 3 + 0] * J[j][0] + cR[j][r * 3 + 1] * J[j][1]
                                 + cR[j][r * 3 + 2] * J[j][2]);
            g_relT[b * 60 + j * 12 + r * 4 + 0] = cR[j][r * 3 + 0];
            g_relT[b * 60 + j * 12 + r * 4 + 1] = cR[j][r * 3 + 1];
            g_relT[b * 60 + j * 12 + r * 4 + 2] = cR[j][r * 3 + 2];
            g_relT[b * 60 + j * 12 + r * 4 + 3] = tr;
        }
}

// ============================================================
// kernT: transpose posedirs [36 x 15069] -> g_pdT [15069 x 36]
// ============================================================
__global__ void kernT(const float* __restrict__ pd)
{
    __shared__ float s[36][65];
    int n0 = blockIdx.x * 64;
    for (int idx = threadIdx.x; idx < 36 * 64; idx += 256) {
        int k = idx / 64, i = idx % 64;
        int n = n0 + i;
        s[k][i] = (n < PD_N) ? pd[k * PD_N + n] : 0.f;
    }
    __syncthreads();
    for (int idx = threadIdx.x; idx < 64 * 36; idx += 256) {
        int i = idx / 36, k = idx % 36;
        int n = n0 + i;
        if (n < PD_N) g_pdT[(size_t)n * 36 + k] = s[k][i];
    }
}

// ============================================================
// Prep: A [1024 x 192] bf16, B4 [20096 x 192] bf16 (row n = 4v+c)
// ============================================================
__global__ void kernPA(const float* __restrict__ shape, const float* __restrict__ expr)
{
    int b = blockIdx.x, k = threadIdx.x;
    float v = 0.f;
    if (k < NSHAPE)               v = shape[b * NSHAPE + k];
    else if (k < NBETA)           v = expr[b * NEXPR + (k - NSHAPE)];
    else if (k < NBETA + NPOSE)   v = g_pf[b * NPOSE + (k - NBETA)];
    g_A[b * KP + k] = __float2bfloat16(v);
}

__global__ void kernPB4(const float* __restrict__ sd)
{
    int n = blockIdx.x, k = threadIdx.x;
    int v = n >> 2, c = n & 3;
    float val = 0.f;
    if (v < VNUM && c < 3) {
        if (k < NBETA)              val = sd[v * 450 + c * NBETA + k];
        else if (k < NBETA + NPOSE) val = g_pdT[(size_t)(v * 3 + c) * 36 + (k - NBETA)];
    }
    g_B4[(size_t)n * KP + k] = __float2bfloat16(val);
}

// ============================================================
// kernG: C[128b x 128n] = A @ B4^T via mma.sync bf16 + fused LBS epilogue
// 256 threads (8 warps, 4x2), K=192 fully smem-resident.
// smem: mainloop A@0 (51200B, pitch 400), B@51200 (51200B)
//       epilogue C@0 (128x132 f32 = 67584B), relT@67584 (30720B),
//                w@98304 (640B), vt@98944 (384B)
// ============================================================
#define SM_TOT 102400

__global__ void __launch_bounds__(256, 1) kernG(
    const float* __restrict__ vt, const float* __restrict__ lw,
    float* __restrict__ out)
{
    extern __shared__ char smr[];
    uint32_t sb = smem_u32(smr);
    int tid = threadIdx.x;
    int lane = tid & 31, w = tid >> 5;
    int wm = w & 3, wn = w >> 2;
    int n0 = blockIdx.x * 128;
    int b0 = blockIdx.y * 128;
    int v0 = n0 >> 2;

    // --- stage A,B tiles (each 128 rows x 24 uint4, pitch 400B) ---
    const uint4* gA4 = (const uint4*)(g_A + (size_t)b0 * KP);
    const uint4* gB4 = (const uint4*)(g_B4 + (size_t)n0 * KP);
    for (int i = tid; i < 128 * 24; i += 256) {
        int row = i / 24, q = i - row * 24;
        *(uint4*)(smr + row * 400 + q * 16) = gA4[i];
        *(uint4*)(smr + 51200 + row * 400 + q * 16) = gB4[i];
    }
    __syncthreads();

    float acc[2][8][4];
#pragma unroll
    for (int a = 0; a < 2; a++)
#pragma unroll
        for (int j = 0; j < 8; j++)
#pragma unroll
            for (int k = 0; k < 4; k++) acc[a][j][k] = 0.f;

    int lrow = lane & 15;
    uint32_t koff = (uint32_t)((lane >> 4) * 16);
    uint32_t aBase = sb + (wm * 32 + lrow) * 400 + koff;
    uint32_t bBase = sb + 51200u + (wn * 64 + lrow) * 400 + koff;

#pragma unroll
    for (int ks = 0; ks < 12; ks++) {
        uint32_t kb = (uint32_t)ks * 32u;
        uint32_t ra[2][4], rb[4][4];
        LDSM4(ra[0][0], ra[0][1], ra[0][2], ra[0][3], aBase + kb);
        LDSM4(ra[1][0], ra[1][1], ra[1][2], ra[1][3], aBase + 16 * 400 + kb);
#pragma unroll
        for (int jj = 0; jj < 4; jj++)
            LDSM4(rb[jj][0], rb[jj][1], rb[jj][2], rb[jj][3], bBase + jj * (16 * 400) + kb);
#pragma unroll
        for (int a = 0; a < 2; a++)
#pragma unroll
            for (int jj = 0; jj < 4; jj++) {
                MMA16816(acc[a][jj * 2],     ra[a][0], ra[a][1], ra[a][2], ra[a][3],
                         rb[jj][0], rb[jj][2]);
                MMA16816(acc[a][jj * 2 + 1], ra[a][0], ra[a][1], ra[a][2], ra[a][3],
                         rb[jj][1], rb[jj][3]);
            }
    }

    __syncthreads();   // done reading A/B smem

    // --- write accumulators to sC [128 x 132] f32 ---
    float* sC = (float*)smr;
#pragma unroll
    for (int a = 0; a < 2; a++) {
        int r = wm * 32 + a * 16 + (lane >> 2);
        int cb = wn * 64 + (lane & 3) * 2;
#pragma unroll
        for (int j = 0; j < 8; j++) {
            int c = cb + j * 8;
            sC[r * 132 + c]           = acc[a][j][0];
            sC[r * 132 + c + 1]       = acc[a][j][1];
            sC[(r + 8) * 132 + c]     = acc[a][j][2];
            sC[(r + 8) * 132 + c + 1] = acc[a][j][3];
        }
    }

    // --- stage relT / weights / template ---
    float* sRT = (float*)(smr + 67584);
    for (int i = tid; i < 128 * 60; i += 256) sRT[i] = g_relT[b0 * 60 + i];
    float* sW = (float*)(smr + 98304);
    if (tid < 32 * NJ) {
        int vl = tid / NJ;
        int v = v0 + vl;
        sW[tid] = (v < VNUM) ? lw[v * NJ + (tid % NJ)] : 0.f;
    }
    float* sVT = (float*)(smr + 98944);
    if (tid < 96) {
        int vl = tid / 3;
        int v = v0 + vl;
        sVT[tid] = (v < VNUM) ? vt[v * 3 + (tid % 3)] : 0.f;
    }
    __syncthreads();

    // --- per (b, v): blend transform, apply, write out ---
#pragma unroll 4
    for (int it = 0; it < 16; it++) {
        int p = it * 256 + tid;
        int vl = p & 31, bl = p >> 5;
        int v = v0 + vl;
        float4 cv = *(const float4*)(sC + bl * 132 + vl * 4);
        const float* rt = sRT + bl * 60;
        float w0 = sW[vl * NJ + 0], w1 = sW[vl * NJ + 1], w2 = sW[vl * NJ + 2];
        float w3 = sW[vl * NJ + 3], w4 = sW[vl * NJ + 4];
        float T[12];
#pragma unroll
        for (int k = 0; k < 12; k++)
            T[k] = fmaf(w0, rt[k], fmaf(w1, rt[12 + k], fmaf(w2, rt[24 + k],
                   fmaf(w3, rt[36 + k], w4 * rt[48 + k]))));
        float px = cv.x + sVT[vl * 3 + 0];
        float py = cv.y + sVT[vl * 3 + 1];
        float pz = cv.z + sVT[vl * 3 + 2];
        float ox = fmaf(T[0], px, fmaf(T[1],  py, fmaf(T[2],  pz, T[3])));
        float oy = fmaf(T[4], px, fmaf(T[5],  py, fmaf(T[6],  pz, T[7])));
        float oz = fmaf(T[8], px, fmaf(T[9],  py, fmaf(T[10], pz, T[11])));
        if (v < VNUM) {
            size_t base = ((size_t)(b0 + bl) * VNUM + v) * 3;
            out[base + 0] = ox; out[base + 1] = oy; out[base + 2] = oz;
        }
    }
}

// ============================================================
// Landmark gather
// ============================================================
__global__ void kernD(const int* __restrict__ land, const float* __restrict__ verts,
                      float* __restrict__ lmk)
{
    int i = blockIdx.x * blockDim.x + threadIdx.x;
    if (i >= NB * NLMK) return;
    int b = i / NLMK, k = i % NLMK;
    int v = land[k];
    size_t src = ((size_t)b * VNUM + v) * 3;
    size_t dst = (size_t)i * 3;
    lmk[dst + 0] = verts[src + 0];
    lmk[dst + 1] = verts[src + 1];
    lmk[dst + 2] = verts[src + 2];
}

// ============================================================
extern "C" void kernel_launch(void* const* d_in, const int* in_sizes, int n_in,
                              void* d_out, int out_size)
{
    const float* shape = (const float*)d_in[0];
    const float* expr  = (const float*)d_in[1];
    const float* pose  = (const float*)d_in[2];
    const int*   land  = (const int*)  d_in[3];
    const float* vt    = (const float*)d_in[4];
    const float* sd    = (const float*)d_in[5];
    const float* pd    = (const float*)d_in[6];
    const float* Jreg  = (const float*)d_in[7];
    const float* lw    = (const float*)d_in[8];
    const float* eye   = (const float*)d_in[9];
    const float* neck  = (const float*)d_in[10];
    float* out = (float*)d_out;

    cudaFuncSetAttribute(kernG, cudaFuncAttributeMaxDynamicSharedMemorySize, SM_TOT);

    kernA<<<NCHUNK, 256>>>(sd, vt, Jreg);
    kernA2<<<NJ, 512>>>();
    kernB<<<NB / 128, 128>>>(shape, expr, pose, eye, neck);
    kernT<<<(PD_N + 63) / 64, 256>>>(pd);
    kernPA<<<NB, KP>>>(shape, expr);
    kernPB4<<<NPAD4, KP>>>(sd);

    dim3 gg(NPAD4 / 128, NB / 128);
    kernG<<<gg, 256, SM_TOT>>>(vt, lw, out);

    float* lmk = out + (size_t)NB * VNUM * 3;
    kernD<<<(NB * NLMK + 255) / 256, 256>>>(land, out, lmk);
}

// round 4
// speedup vs baseline: 2.5609x; 1.0198x over previous
#include <cuda_runtime.h>
#include <cuda_bf16.h>
#include <math.h>
#include <stdint.h>

#define VNUM   5023
#define NJ     5
#define NB     1024
#define NSHAPE 100
#define NEXPR  50
#define NBETA  150
#define NLMK   68
#define NPOSE  36
#define JR_COLS 453
#define NCHUNK 64
#define CHUNK_V 79
#define PD_N   (VNUM * 3)      // 15069

#define KP    192              // padded K: 150 betas + 36 pose feats + 6 zero
#define NPAD4 20096            // 157 * 128 >= 4*VNUM

// ---- device scratch ----
__device__ float g_partial[NCHUNK * NJ * JR_COLS];
__device__ float g_Jr[NJ * JR_COLS];
__device__ float g_pf[NB * NPOSE];
__device__ float g_relT[NB * NJ * 12];
__device__ __nv_bfloat16 g_A[NB * KP];                // 0.4 MB
__device__ __nv_bfloat16 g_B4[(size_t)NPAD4 * KP];    // 7.7 MB

__device__ __forceinline__ uint32_t smem_u32(const void* p) {
    uint32_t a;
    asm("{ .reg .u64 t; cvta.to.shared.u64 t, %1; cvt.u32.u64 %0, t; }" : "=r"(a) : "l"(p));
    return a;
}

#define LDSM4(R0, R1, R2, R3, ADDR) \
    asm volatile("ldmatrix.sync.aligned.m8n8.x4.shared.b16 {%0,%1,%2,%3}, [%4];" \
        : "=r"(R0), "=r"(R1), "=r"(R2), "=r"(R3) : "r"(ADDR))

#define MMA16816(C, A0, A1, A2, A3, B0, B1) \
    asm volatile("mma.sync.aligned.m16n8k16.row.col.f32.bf16.bf16.f32 " \
        "{%0,%1,%2,%3},{%4,%5,%6,%7},{%8,%9},{%0,%1,%2,%3};" \
        : "+f"((C)[0]), "+f"((C)[1]), "+f"((C)[2]), "+f"((C)[3]) \
        : "r"(A0), "r"(A1), "r"(A2), "r"(A3), "r"(B0), "r"(B1))

#define CP_ASYNC16(DST, SRC) \
    asm volatile("cp.async.cg.shared.global [%0], [%1], 16;" :: "r"(DST), "l"(SRC))
#define CP_ASYNC_WAIT() \
    asm volatile("cp.async.commit_group;\n\tcp.async.wait_group 0;" ::: "memory")

// ============================================================
// Kernel A: partial sums of Jreg @ [shapedirs | v_template]
// ============================================================
__global__ void kernA(const float* __restrict__ sd, const float* __restrict__ vt,
                      const float* __restrict__ Jreg)
{
    __shared__ float s_jr[NJ * CHUNK_V];
    int chunk = blockIdx.x;
    int v0 = chunk * CHUNK_V;
    int nv = VNUM - v0; if (nv > CHUNK_V) nv = CHUNK_V; if (nv < 0) nv = 0;

    for (int i = threadIdx.x; i < NJ * CHUNK_V; i += blockDim.x) {
        int j = i / CHUNK_V, vv = i % CHUNK_V;
        s_jr[i] = (vv < nv) ? Jreg[j * VNUM + v0 + vv] : 0.f;
    }
    __syncthreads();

    int col0 = threadIdx.x;
    int col1 = threadIdx.x + 256;
    float acc0[NJ], acc1[NJ];
#pragma unroll
    for (int j = 0; j < NJ; j++) { acc0[j] = 0.f; acc1[j] = 0.f; }

    for (int vv = 0; vv < nv; vv++) {
        int v = v0 + vv;
        float x0 = (col0 < 450) ? sd[v * 450 + col0] : vt[v * 3 + (col0 - 450)];
#pragma unroll
        for (int j = 0; j < NJ; j++) acc0[j] = fmaf(s_jr[j * CHUNK_V + vv], x0, acc0[j]);
        if (col1 < JR_COLS) {
            float x1 = (col1 < 450) ? sd[v * 450 + col1] : vt[v * 3 + (col1 - 450)];
#pragma unroll
            for (int j = 0; j < NJ; j++) acc1[j] = fmaf(s_jr[j * CHUNK_V + vv], x1, acc1[j]);
        }
    }
#pragma unroll
    for (int j = 0; j < NJ; j++) {
        g_partial[(chunk * NJ + j) * JR_COLS + col0] = acc0[j];
        if (col1 < JR_COLS) g_partial[(chunk * NJ + j) * JR_COLS + col1] = acc1[j];
    }
}

__global__ void kernA2()
{
    int j = blockIdx.x;
    int col = threadIdx.x;
    if (col >= JR_COLS) return;
    float s = 0.f;
    for (int ch = 0; ch < NCHUNK; ch++) s += g_partial[(ch * NJ + j) * JR_COLS + col];
    g_Jr[j * JR_COLS + col] = s;
}

// ============================================================
// Kernel B: per-batch joints, Rodrigues, kinematic chain
// ============================================================
__global__ void kernB(const float* __restrict__ shape, const float* __restrict__ expr,
                      const float* __restrict__ pose, const float* __restrict__ eye,
                      const float* __restrict__ neck)
{
    __shared__ float s_jr[NJ * JR_COLS];
    for (int i = threadIdx.x; i < NJ * JR_COLS; i += blockDim.x) s_jr[i] = g_Jr[i];
    __syncthreads();

    int b = blockIdx.x * blockDim.x + threadIdx.x;
    if (b >= NB) return;

    float J[NJ][3];
#pragma unroll
    for (int j = 0; j < NJ; j++)
#pragma unroll
        for (int c = 0; c < 3; c++) J[j][c] = s_jr[j * JR_COLS + 450 + c];

    for (int l = 0; l < NBETA; l++) {
        float bl = (l < NSHAPE) ? shape[b * NSHAPE + l] : expr[b * NEXPR + l - NSHAPE];
#pragma unroll
        for (int j = 0; j < NJ; j++)
#pragma unroll
            for (int c = 0; c < 3; c++) J[j][c] = fmaf(s_jr[j * JR_COLS + l], bl, J[j][c]);
    }

    float fp[15];
    fp[0] = pose[b * 6 + 0]; fp[1] = pose[b * 6 + 1]; fp[2] = pose[b * 6 + 2];
    fp[3] = neck[0]; fp[4] = neck[1]; fp[5] = neck[2];
    fp[6] = pose[b * 6 + 3]; fp[7] = pose[b * 6 + 4]; fp[8] = pose[b * 6 + 5];
#pragma unroll
    for (int k = 0; k < 6; k++) fp[9 + k] = eye[k];

    float R[NJ][9];
#pragma unroll
    for (int j = 0; j < NJ; j++) {
        float x = fp[j * 3 + 0], y = fp[j * 3 + 1], z = fp[j * 3 + 2];
        float xa = x + 1e-8f, ya = y + 1e-8f, za = z + 1e-8f;
        float ang = sqrtf(xa * xa + ya * ya + za * za);
        float inv = 1.f / ang;
        float rx = x * inv, ry = y * inv, rz = z * inv;
        float s, c;
        sincosf(ang, &s, &c);
        float t = 1.f - c;
        R[j][0] = 1.f - t * (ry * ry + rz * rz);
        R[j][1] = -s * rz + t * rx * ry;
        R[j][2] =  s * ry + t * rx * rz;
        R[j][3] =  s * rz + t * rx * ry;
        R[j][4] = 1.f - t * (rx * rx + rz * rz);
        R[j][5] = -s * rx + t * ry * rz;
        R[j][6] = -s * ry + t * rx * rz;
        R[j][7] =  s * rx + t * ry * rz;
        R[j][8] = 1.f - t * (rx * rx + ry * ry);
    }

#pragma unroll
    for (int j = 1; j < NJ; j++)
#pragma unroll
        for (int k = 0; k < 9; k++) {
            float d = (k == 0 || k == 4 || k == 8) ? 1.f : 0.f;
            g_pf[b * NPOSE + (j - 1) * 9 + k] = R[j][k] - d;
        }

    const int par[NJ] = { -1, 0, 1, 1, 1 };
    float rel[NJ][3];
#pragma unroll
    for (int c = 0; c < 3; c++) rel[0][c] = J[0][c];
#pragma unroll
    for (int j = 1; j < NJ; j++)
#pragma unroll
        for (int c = 0; c < 3; c++) rel[j][c] = J[j][c] - J[par[j]][c];

    float cR[NJ][9], ct[NJ][3];
#pragma unroll
    for (int k = 0; k < 9; k++) cR[0][k] = R[0][k];
#pragma unroll
    for (int c = 0; c < 3; c++) ct[0][c] = rel[0][c];
#pragma unroll
    for (int j = 1; j < NJ; j++) {
        int p = par[j];
#pragma unroll
        for (int r = 0; r < 3; r++) {
#pragma unroll
            for (int c = 0; c < 3; c++)
                cR[j][r * 3 + c] = cR[p][r * 3 + 0] * R[j][0 + c]
                                 + cR[p][r * 3 + 1] * R[j][3 + c]
                                 + cR[p][r * 3 + 2] * R[j][6 + c];
            ct[j][r] = cR[p][r * 3 + 0] * rel[j][0] + cR[p][r * 3 + 1] * rel[j][1]
                     + cR[p][r * 3 + 2] * rel[j][2] + ct[p][r];
        }
    }

#pragma unroll
    for (int j = 0; j < NJ; j++)
#pragma unroll
        for (int r = 0; r < 3; r++) {
            float tr = ct[j][r] - (cR[j][r * 3 + 0] * J[j][0] + cR[j][r * 3 + 1] * J[j][1]
                                 + cR[j][r * 3 + 2] * J[j][2]);
            g_relT[b * 60 + j * 12 + r * 4 + 0] = cR[j][r * 3 + 0];
            g_relT[b * 60 + j * 12 + r * 4 + 1] = cR[j][r * 3 + 1];
            g_relT[b * 60 + j * 12 + r * 4 + 2] = cR[j][r * 3 + 2];
            g_relT[b * 60 + j * 12 + r * 4 + 3] = tr;
        }
}

// ============================================================
// Prep: A [1024 x 192] bf16, B4 [20096 x 192] bf16 (row n = 4v+c)
// posedirs read directly (column-strided; pd is L2-resident, 2.2MB)
// ============================================================
__global__ void kernPA(const float* __restrict__ shape, const float* __restrict__ expr)
{
    int b = blockIdx.x, k = threadIdx.x;
    float v = 0.f;
    if (k < NSHAPE)               v = shape[b * NSHAPE + k];
    else if (k < NBETA)           v = expr[b * NEXPR + (k - NSHAPE)];
    else if (k < NBETA + NPOSE)   v = g_pf[b * NPOSE + (k - NBETA)];
    g_A[b * KP + k] = __float2bfloat16(v);
}

__global__ void kernPB4(const float* __restrict__ sd, const float* __restrict__ pd)
{
    int n = blockIdx.x, k = threadIdx.x;
    int v = n >> 2, c = n & 3;
    float val = 0.f;
    if (v < VNUM && c < 3) {
        if (k < NBETA)              val = sd[v * 450 + c * NBETA + k];
        else if (k < NBETA + NPOSE) val = pd[(size_t)(k - NBETA) * PD_N + (v * 3 + c)];
    }
    g_B4[(size_t)n * KP + k] = __float2bfloat16(val);
}

// ============================================================
// kernG: C[64b x 128n] = A @ B4^T via mma.sync bf16 + fused LBS epilogue
// 256 threads (8 warps as 2x4), K=192 fully smem-resident, cp.async staging.
// smem: A@0 (64 rows x 400B = 25600), B@25600 (128 x 400B = 51200) -> 76800 B
// epilogue reuses: sC@0 (64x132 f32 = 33792), relT@33792 (15360),
//                  w@49152 (640), vt@49792 (384)
// ============================================================
#define SMB_OFF 25600
#define SM_TOT  76800

__global__ void __launch_bounds__(256, 2) kernG(
    const float* __restrict__ vt, const float* __restrict__ lw,
    float* __restrict__ out)
{
    extern __shared__ char smr[];
    uint32_t sb = smem_u32(smr);
    int tid = threadIdx.x;
    int lane = tid & 31, w = tid >> 5;
    int wm = w & 1, wn = w >> 1;          // 2 x 4 warp grid, warp tile 32b x 32n
    int n0 = blockIdx.x * 128;
    int b0 = blockIdx.y * 64;
    int v0 = n0 >> 2;

    // --- stage A (64x24 uint4) and B (128x24 uint4) via cp.async, pitch 400B ---
    {
        const uint4* gA4 = (const uint4*)(g_A + (size_t)b0 * KP);
        const uint4* gB4 = (const uint4*)(g_B4 + (size_t)n0 * KP);
        for (int i = tid; i < 64 * 24; i += 256) {
            int row = i / 24, q = i - row * 24;
            CP_ASYNC16(sb + row * 400 + q * 16, gA4 + i);
        }
        for (int i = tid; i < 128 * 24; i += 256) {
            int row = i / 24, q = i - row * 24;
            CP_ASYNC16(sb + SMB_OFF + row * 400 + q * 16, gB4 + i);
        }
        CP_ASYNC_WAIT();
    }
    __syncthreads();

    float acc[2][4][4];
#pragma unroll
    for (int a = 0; a < 2; a++)
#pragma unroll
        for (int j = 0; j < 4; j++)
#pragma unroll
            for (int k = 0; k < 4; k++) acc[a][j][k] = 0.f;

    int lrow = lane & 15;
    uint32_t koff = (uint32_t)((lane >> 4) * 16);
    uint32_t aBase = sb + (wm * 32 + lrow) * 400 + koff;
    uint32_t bBase = sb + SMB_OFF + (wn * 32 + lrow) * 400 + koff;

#pragma unroll
    for (int ks = 0; ks < 12; ks++) {
        uint32_t kb = (uint32_t)ks * 32u;
        uint32_t ra[2][4], rb[2][4];
        LDSM4(ra[0][0], ra[0][1], ra[0][2], ra[0][3], aBase + kb);
        LDSM4(ra[1][0], ra[1][1], ra[1][2], ra[1][3], aBase + 16 * 400 + kb);
        LDSM4(rb[0][0], rb[0][1], rb[0][2], rb[0][3], bBase + kb);
        LDSM4(rb[1][0], rb[1][1], rb[1][2], rb[1][3], bBase + 16 * 400 + kb);
#pragma unroll
        for (int a = 0; a < 2; a++)
#pragma unroll
            for (int jj = 0; jj < 2; jj++) {
                MMA16816(acc[a][jj * 2],     ra[a][0], ra[a][1], ra[a][2], ra[a][3],
                         rb[jj][0], rb[jj][2]);
                MMA16816(acc[a][jj * 2 + 1], ra[a][0], ra[a][1], ra[a][2], ra[a][3],
                         rb[jj][1], rb[jj][3]);
            }
    }

    __syncthreads();   // done reading A/B smem

    // --- write accumulators to sC [64 x 132] f32 ---
    float* sC = (float*)smr;
#pragma unroll
    for (int a = 0; a < 2; a++) {
        int r = wm * 32 + a * 16 + (lane >> 2);
        int cb = wn * 32 + (lane & 3) * 2;
#pragma unroll
        for (int j = 0; j < 4; j++) {
            int c = cb + j * 8;
            sC[r * 132 + c]           = acc[a][j][0];
            sC[r * 132 + c + 1]       = acc[a][j][1];
            sC[(r + 8) * 132 + c]     = acc[a][j][2];
            sC[(r + 8) * 132 + c + 1] = acc[a][j][3];
        }
    }

    // --- stage relT / weights / template ---
    float* sRT = (float*)(smr + 33792);
    for (int i = tid; i < 64 * 60; i += 256) sRT[i] = g_relT[b0 * 60 + i];
    float* sW = (float*)(smr + 49152);
    if (tid < 32 * NJ) {
        int vl = tid / NJ;
        int v = v0 + vl;
        sW[tid] = (v < VNUM) ? lw[v * NJ + (tid % NJ)] : 0.f;
    }
    float* sVT = (float*)(smr + 49792);
    if (tid < 96) {
        int vl = tid / 3;
        int v = v0 + vl;
        sVT[tid] = (v < VNUM) ? vt[v * 3 + (tid % 3)] : 0.f;
    }
    __syncthreads();

    // --- per (b, v): blend transform (float4 vectorized), apply, write out ---
#pragma unroll
    for (int it = 0; it < 8; it++) {
        int p = it * 256 + tid;
        int vl = p & 31, bl = p >> 5;       // warp-uniform bl
        int v = v0 + vl;
        float4 cv = *(const float4*)(sC + bl * 132 + vl * 4);
        const float4* rt4 = (const float4*)(sRT + bl * 60);   // 15 float4 = 5 joints x 3 rows
        float w0 = sW[vl * NJ + 0], w1 = sW[vl * NJ + 1], w2 = sW[vl * NJ + 2];
        float w3 = sW[vl * NJ + 3], w4 = sW[vl * NJ + 4];
        float4 T4[3];
#pragma unroll
        for (int q = 0; q < 3; q++) {
            float4 r0 = rt4[q], r1 = rt4[3 + q], r2 = rt4[6 + q];
            float4 r3 = rt4[9 + q], r4 = rt4[12 + q];
            T4[q].x = fmaf(w0, r0.x, fmaf(w1, r1.x, fmaf(w2, r2.x, fmaf(w3, r3.x, w4 * r4.x))));
            T4[q].y = fmaf(w0, r0.y, fmaf(w1, r1.y, fmaf(w2, r2.y, fmaf(w3, r3.y, w4 * r4.y))));
            T4[q].z = fmaf(w0, r0.z, fmaf(w1, r1.z, fmaf(w2, r2.z, fmaf(w3, r3.z, w4 * r4.z))));
            T4[q].w = fmaf(w0, r0.w, fmaf(w1, r1.w, fmaf(w2, r2.w, fmaf(w3, r3.w, w4 * r4.w))));
        }
        float px = cv.x + sVT[vl * 3 + 0];
        float py = cv.y + sVT[vl * 3 + 1];
        float pz = cv.z + sVT[vl * 3 + 2];
        float ox = fmaf(T4[0].x, px, fmaf(T4[0].y, py, fmaf(T4[0].z, pz, T4[0].w)));
        float oy = fmaf(T4[1].x, px, fmaf(T4[1].y, py, fmaf(T4[1].z, pz, T4[1].w)));
        float oz = fmaf(T4[2].x, px, fmaf(T4[2].y, py, fmaf(T4[2].z, pz, T4[2].w)));
        if (v < VNUM) {
            size_t base = ((size_t)(b0 + bl) * VNUM + v) * 3;
            out[base + 0] = ox; out[base + 1] = oy; out[base + 2] = oz;
        }
    }
}

// ============================================================
// Landmark gather
// ============================================================
__global__ void kernD(const int* __restrict__ land, const float* __restrict__ verts,
                      float* __restrict__ lmk)
{
    int i = blockIdx.x * blockDim.x + threadIdx.x;
    if (i >= NB * NLMK) return;
    int b = i / NLMK, k = i % NLMK;
    int v = land[k];
    size_t src = ((size_t)b * VNUM + v) * 3;
    size_t dst = (size_t)i * 3;
    lmk[dst + 0] = verts[src + 0];
    lmk[dst + 1] = verts[src + 1];
    lmk[dst + 2] = verts[src + 2];
}

// ============================================================
extern "C" void kernel_launch(void* const* d_in, const int* in_sizes, int n_in,
                              void* d_out, int out_size)
{
    const float* shape = (const float*)d_in[0];
    const float* expr  = (const float*)d_in[1];
    const float* pose  = (const float*)d_in[2];
    const int*   land  = (const int*)  d_in[3];
    const float* vt    = (const float*)d_in[4];
    const float* sd    = (const float*)d_in[5];
    const float* pd    = (const float*)d_in[6];
    const float* Jreg  = (const float*)d_in[7];
    const float* lw    = (const float*)d_in[8];
    const float* eye   = (const float*)d_in[9];
    const float* neck  = (const float*)d_in[10];
    float* out = (float*)d_out;

    cudaFuncSetAttribute(kernG, cudaFuncAttributeMaxDynamicSharedMemorySize, SM_TOT);

    kernA<<<NCHUNK, 256>>>(sd, vt, Jreg);
    kernA2<<<NJ, 512>>>();
    kernB<<<NB / 128, 128>>>(shape, expr, pose, eye, neck);
    kernPA<<<NB, KP>>>(shape, expr);
    kernPB4<<<NPAD4, KP>>>(sd, pd);

    dim3 gg(NPAD4 / 128, NB / 64);
    kernG<<<gg, 256, SM_TOT>>>(vt, lw, out);

    float* lmk = out + (size_t)NB * VNUM * 3;
    kernD<<<(NB * NLMK + 255) / 256, 256>>>(land, out, lmk);
}

// round 5
// speedup vs baseline: 2.5910x; 1.0117x over previous
#include <cuda_runtime.h>
#include <cuda_bf16.h>
#include <math.h>
#include <stdint.h>

#define VNUM   5023
#define NJ     5
#define NB     1024
#define NSHAPE 100
#define NEXPR  50
#define NBETA  150
#define NLMK   68
#define NPOSE  36
#define JR_COLS 453
#define NCHUNK 64
#define CHUNK_V 79
#define PD_N   (VNUM * 3)      // 15069

#define KP    192              // padded K: 150 betas + 36 pose feats + 6 zero
#define NPAD4 20096            // 157 * 128 >= 4*VNUM

// ---- device scratch ----
__device__ float g_Jr[NJ * JR_COLS];
__device__ float g_relT[NB * NJ * 12];
__device__ __nv_bfloat16 g_A[NB * KP];                // 0.4 MB
__device__ __nv_bfloat16 g_B4[(size_t)NPAD4 * KP];    // 7.7 MB

__device__ __forceinline__ uint32_t smem_u32(const void* p) {
    uint32_t a;
    asm("{ .reg .u64 t; cvta.to.shared.u64 t, %1; cvt.u32.u64 %0, t; }" : "=r"(a) : "l"(p));
    return a;
}

#define LDSM4(R0, R1, R2, R3, ADDR) \
    asm volatile("ldmatrix.sync.aligned.m8n8.x4.shared.b16 {%0,%1,%2,%3}, [%4];" \
        : "=r"(R0), "=r"(R1), "=r"(R2), "=r"(R3) : "r"(ADDR))

#define MMA16816(C, A0, A1, A2, A3, B0, B1) \
    asm volatile("mma.sync.aligned.m16n8k16.row.col.f32.bf16.bf16.f32 " \
        "{%0,%1,%2,%3},{%4,%5,%6,%7},{%8,%9},{%0,%1,%2,%3};" \
        : "+f"((C)[0]), "+f"((C)[1]), "+f"((C)[2]), "+f"((C)[3]) \
        : "r"(A0), "r"(A1), "r"(A2), "r"(A3), "r"(B0), "r"(B1))

#define CP_ASYNC16(DST, SRC) \
    asm volatile("cp.async.cg.shared.global [%0], [%1], 16;" :: "r"(DST), "l"(SRC))
#define CP_ASYNC_WAIT() \
    asm volatile("cp.async.commit_group;\n\tcp.async.wait_group 0;" ::: "memory")

// ============================================================
// Launch 1 — kernPB4: build B4 [20096 x 192] bf16 (row n = 4v+c).
// Block 0 additionally zeroes g_Jr (kernA accumulates into it next).
// ============================================================
__global__ void kernPB4(const float* __restrict__ sd, const float* __restrict__ pd)
{
    int n = blockIdx.x, k = threadIdx.x;
    if (blockIdx.x == 0) {
        for (int i = threadIdx.x; i < NJ * JR_COLS; i += blockDim.x) g_Jr[i] = 0.f;
    }
    int v = n >> 2, c = n & 3;
    float val = 0.f;
    if (v < VNUM && c < 3) {
        if (k < NBETA)              val = sd[v * 450 + c * NBETA + k];
        else if (k < NBETA + NPOSE) val = pd[(size_t)(k - NBETA) * PD_N + (v * 3 + c)];
    }
    g_B4[(size_t)n * KP + k] = __float2bfloat16(val);
}

// ============================================================
// Launch 2 — kernA: g_Jr += Jreg-chunk @ [shapedirs | v_template]
// via float atomics (order-nondeterminism ~ULP, far below tolerance).
// ============================================================
__global__ void kernA(const float* __restrict__ sd, const float* __restrict__ vt,
                      const float* __restrict__ Jreg)
{
    __shared__ float s_jr[NJ * CHUNK_V];
    int chunk = blockIdx.x;
    int v0 = chunk * CHUNK_V;
    int nv = VNUM - v0; if (nv > CHUNK_V) nv = CHUNK_V; if (nv < 0) nv = 0;

    for (int i = threadIdx.x; i < NJ * CHUNK_V; i += blockDim.x) {
        int j = i / CHUNK_V, vv = i % CHUNK_V;
        s_jr[i] = (vv < nv) ? Jreg[j * VNUM + v0 + vv] : 0.f;
    }
    __syncthreads();

    int col0 = threadIdx.x;
    int col1 = threadIdx.x + 256;
    float acc0[NJ], acc1[NJ];
#pragma unroll
    for (int j = 0; j < NJ; j++) { acc0[j] = 0.f; acc1[j] = 0.f; }

    for (int vv = 0; vv < nv; vv++) {
        int v = v0 + vv;
        float x0 = (col0 < 450) ? sd[v * 450 + col0] : vt[v * 3 + (col0 - 450)];
#pragma unroll
        for (int j = 0; j < NJ; j++) acc0[j] = fmaf(s_jr[j * CHUNK_V + vv], x0, acc0[j]);
        if (col1 < JR_COLS) {
            float x1 = (col1 < 450) ? sd[v * 450 + col1] : vt[v * 3 + (col1 - 450)];
#pragma unroll
            for (int j = 0; j < NJ; j++) acc1[j] = fmaf(s_jr[j * CHUNK_V + vv], x1, acc1[j]);
        }
    }
#pragma unroll
    for (int j = 0; j < NJ; j++) {
        atomicAdd(&g_Jr[j * JR_COLS + col0], acc0[j]);
        if (col1 < JR_COLS) atomicAdd(&g_Jr[j * JR_COLS + col1], acc1[j]);
    }
}

// ============================================================
// Launch 3 — kernB: joints, Rodrigues, chain -> g_relT; ALSO builds
// bf16 A rows (betas|pose_feature) -> g_A  (merged former kernPA).
// Betas staged coalesced into smem, pitch 153 (conflict-free).
// dyn smem: s_jr@0 (2272 floats), s_beta@2272 (128*153 floats)
// ============================================================
#define BP 153
#define KB_SMEM ((2272 + 128 * BP) * 4)

__global__ void kernB(const float* __restrict__ shape, const float* __restrict__ expr,
                      const float* __restrict__ pose, const float* __restrict__ eye,
                      const float* __restrict__ neck)
{
    extern __shared__ float smf[];
    float* s_jr   = smf;
    float* s_beta = smf + 2272;
    int tid = threadIdx.x;
    int b0 = blockIdx.x * 128;

    for (int i = tid; i < NJ * JR_COLS; i += blockDim.x) s_jr[i] = g_Jr[i];
    for (int i = tid; i < 128 * NSHAPE; i += blockDim.x)
        s_beta[(i / NSHAPE) * BP + (i % NSHAPE)] = shape[b0 * NSHAPE + i];
    for (int i = tid; i < 128 * NEXPR; i += blockDim.x)
        s_beta[(i / NEXPR) * BP + NSHAPE + (i % NEXPR)] = expr[b0 * NEXPR + i];
    __syncthreads();

    int bl = tid;              // 0..127
    int b = b0 + bl;
    const float* myb = s_beta + bl * BP;

    float J[NJ][3];
#pragma unroll
    for (int j = 0; j < NJ; j++)
#pragma unroll
        for (int c = 0; c < 3; c++) J[j][c] = s_jr[j * JR_COLS + 450 + c];

    for (int l = 0; l < NBETA; l++) {
        float blv = myb[l];
#pragma unroll
        for (int j = 0; j < NJ; j++)
#pragma unroll
            for (int c = 0; c < 3; c++) J[j][c] = fmaf(s_jr[j * JR_COLS + l], blv, J[j][c]);
    }

    float fp[15];
    fp[0] = pose[b * 6 + 0]; fp[1] = pose[b * 6 + 1]; fp[2] = pose[b * 6 + 2];
    fp[3] = neck[0]; fp[4] = neck[1]; fp[5] = neck[2];
    fp[6] = pose[b * 6 + 3]; fp[7] = pose[b * 6 + 4]; fp[8] = pose[b * 6 + 5];
#pragma unroll
    for (int k = 0; k < 6; k++) fp[9 + k] = eye[k];

    float R[NJ][9];
#pragma unroll
    for (int j = 0; j < NJ; j++) {
        float x = fp[j * 3 + 0], y = fp[j * 3 + 1], z = fp[j * 3 + 2];
        float xa = x + 1e-8f, ya = y + 1e-8f, za = z + 1e-8f;
        float ang = sqrtf(xa * xa + ya * ya + za * za);
        float inv = 1.f / ang;
        float rx = x * inv, ry = y * inv, rz = z * inv;
        float s, c;
        sincosf(ang, &s, &c);
        float t = 1.f - c;
        R[j][0] = 1.f - t * (ry * ry + rz * rz);
        R[j][1] = -s * rz + t * rx * ry;
        R[j][2] =  s * ry + t * rx * rz;
        R[j][3] =  s * rz + t * rx * ry;
        R[j][4] = 1.f - t * (rx * rx + rz * rz);
        R[j][5] = -s * rx + t * ry * rz;
        R[j][6] = -s * ry + t * rx * rz;
        R[j][7] =  s * rx + t * ry * rz;
        R[j][8] = 1.f - t * (rx * rx + ry * ry);
    }

    // --- g_A row: [betas(150) | pose_feature(36) | 0 pad(6)] as bf16 ---
    {
        __nv_bfloat16* arow = g_A + (size_t)b * KP;
#pragma unroll 2
        for (int l = 0; l < NBETA; l++) arow[l] = __float2bfloat16(myb[l]);
#pragma unroll
        for (int j = 1; j < NJ; j++)
#pragma unroll
            for (int k = 0; k < 9; k++) {
                float d = (k == 0 || k == 4 || k == 8) ? 1.f : 0.f;
                arow[NBETA + (j - 1) * 9 + k] = __float2bfloat16(R[j][k] - d);
            }
#pragma unroll
        for (int k = NBETA + NPOSE; k < KP; k++) arow[k] = __float2bfloat16(0.f);
    }

    const int par[NJ] = { -1, 0, 1, 1, 1 };
    float rel[NJ][3];
#pragma unroll
    for (int c = 0; c < 3; c++) rel[0][c] = J[0][c];
#pragma unroll
    for (int j = 1; j < NJ; j++)
#pragma unroll
        for (int c = 0; c < 3; c++) rel[j][c] = J[j][c] - J[par[j]][c];

    float cR[NJ][9], ct[NJ][3];
#pragma unroll
    for (int k = 0; k < 9; k++) cR[0][k] = R[0][k];
#pragma unroll
    for (int c = 0; c < 3; c++) ct[0][c] = rel[0][c];
#pragma unroll
    for (int j = 1; j < NJ; j++) {
        int p = par[j];
#pragma unroll
        for (int r = 0; r < 3; r++) {
#pragma unroll
            for (int c = 0; c < 3; c++)
                cR[j][r * 3 + c] = cR[p][r * 3 + 0] * R[j][0 + c]
                                 + cR[p][r * 3 + 1] * R[j][3 + c]
                                 + cR[p][r * 3 + 2] * R[j][6 + c];
            ct[j][r] = cR[p][r * 3 + 0] * rel[j][0] + cR[p][r * 3 + 1] * rel[j][1]
                     + cR[p][r * 3 + 2] * rel[j][2] + ct[p][r];
        }
    }

#pragma unroll
    for (int j = 0; j < NJ; j++)
#pragma unroll
        for (int r = 0; r < 3; r++) {
            float tr = ct[j][r] - (cR[j][r * 3 + 0] * J[j][0] + cR[j][r * 3 + 1] * J[j][1]
                                 + cR[j][r * 3 + 2] * J[j][2]);
            g_relT[b * 60 + j * 12 + r * 4 + 0] = cR[j][r * 3 + 0];
            g_relT[b * 60 + j * 12 + r * 4 + 1] = cR[j][r * 3 + 1];
            g_relT[b * 60 + j * 12 + r * 4 + 2] = cR[j][r * 3 + 2];
            g_relT[b * 60 + j * 12 + r * 4 + 3] = tr;
        }
}

// ============================================================
// Launch 4 — kernG: C[128b x 128n] = A @ B4^T (mma.sync bf16)
// + fused LBS epilogue.  256 thr = 8 warps (4b x 2n), warp tile 32x64.
// K=192 smem-resident, cp.async staging, 2 CTAs/SM (2 x 100KB).
// smem mainloop: A@0 (128x400B=51200), B@51200 (51200) -> 102400 B
// epilogue reuse: sC@0 (128x132 f32=67584), relT@67584 (30720),
//                 w@98304 (640), vt@98944 (384)
// ============================================================
#define SMB_OFF 51200
#define SM_TOT  102400

__global__ void __launch_bounds__(256, 2) kernG(
    const float* __restrict__ vt, const float* __restrict__ lw,
    float* __restrict__ out)
{
    extern __shared__ char smr[];
    uint32_t sb = smem_u32(smr);
    int tid = threadIdx.x;
    int lane = tid & 31, w = tid >> 5;
    int wm = w & 3, wn = w >> 2;          // 4 x 2 warp grid, warp tile 32b x 64n
    int n0 = blockIdx.x * 128;
    int b0 = blockIdx.y * 128;
    int v0 = n0 >> 2;

    // --- stage A,B tiles (each 128 x 24 uint4, pitch 400B) via cp.async ---
    {
        const uint4* gA4 = (const uint4*)(g_A + (size_t)b0 * KP);
        const uint4* gB4 = (const uint4*)(g_B4 + (size_t)n0 * KP);
        for (int i = tid; i < 128 * 24; i += 256) {
            int row = i / 24, q = i - row * 24;
            CP_ASYNC16(sb + row * 400 + q * 16, gA4 + i);
            CP_ASYNC16(sb + SMB_OFF + row * 400 + q * 16, gB4 + i);
        }
        CP_ASYNC_WAIT();
    }
    __syncthreads();

    float acc[2][8][4];
#pragma unroll
    for (int a = 0; a < 2; a++)
#pragma unroll
        for (int j = 0; j < 8; j++)
#pragma unroll
            for (int k = 0; k < 4; k++) acc[a][j][k] = 0.f;

    int lrow = lane & 15;
    uint32_t koff = (uint32_t)((lane >> 4) * 16);
    uint32_t aBase = sb + (wm * 32 + lrow) * 400 + koff;
    uint32_t bBase = sb + SMB_OFF + (wn * 64 + lrow) * 400 + koff;

#pragma unroll
    for (int ks = 0; ks < 12; ks++) {
        uint32_t kb = (uint32_t)ks * 32u;
        uint32_t ra[2][4], rb[4][4];
        LDSM4(ra[0][0], ra[0][1], ra[0][2], ra[0][3], aBase + kb);
        LDSM4(ra[1][0], ra[1][1], ra[1][2], ra[1][3], aBase + 16 * 400 + kb);
#pragma unroll
        for (int jj = 0; jj < 4; jj++)
            LDSM4(rb[jj][0], rb[jj][1], rb[jj][2], rb[jj][3], bBase + jj * (16 * 400) + kb);
#pragma unroll
        for (int a = 0; a < 2; a++)
#pragma unroll
            for (int jj = 0; jj < 4; jj++) {
                MMA16816(acc[a][jj * 2],     ra[a][0], ra[a][1], ra[a][2], ra[a][3],
                         rb[jj][0], rb[jj][2]);
                MMA16816(acc[a][jj * 2 + 1], ra[a][0], ra[a][1], ra[a][2], ra[a][3],
                         rb[jj][1], rb[jj][3]);
            }
    }

    __syncthreads();   // done reading A/B smem

    // --- write accumulators to sC [128 x 132] f32 ---
    float* sC = (float*)smr;
#pragma unroll
    for (int a = 0; a < 2; a++) {
        int r = wm * 32 + a * 16 + (lane >> 2);
        int cb = wn * 64 + (lane & 3) * 2;
#pragma unroll
        for (int j = 0; j < 8; j++) {
            int c = cb + j * 8;
            sC[r * 132 + c]           = acc[a][j][0];
            sC[r * 132 + c + 1]       = acc[a][j][1];
            sC[(r + 8) * 132 + c]     = acc[a][j][2];
            sC[(r + 8) * 132 + c + 1] = acc[a][j][3];
        }
    }

    // --- stage relT / weights / template ---
    float* sRT = (float*)(smr + 67584);
    for (int i = tid; i < 128 * 60; i += 256) sRT[i] = g_relT[b0 * 60 + i];
    float* sW = (float*)(smr + 98304);
    if (tid < 32 * NJ) {
        int vl = tid / NJ;
        int v = v0 + vl;
        sW[tid] = (v < VNUM) ? lw[v * NJ + (tid % NJ)] : 0.f;
    }
    float* sVT = (float*)(smr + 98944);
    if (tid < 96) {
        int vl = tid / 3;
        int v = v0 + vl;
        sVT[tid] = (v < VNUM) ? vt[v * 3 + (tid % 3)] : 0.f;
    }
    __syncthreads();

    // --- per (b, v): blend transform (float4 vectorized), apply, write out ---
#pragma unroll 4
    for (int it = 0; it < 16; it++) {
        int p = it * 256 + tid;
        int vl = p & 31, bl = p >> 5;       // warp-uniform bl
        int v = v0 + vl;
        float4 cv = *(const float4*)(sC + bl * 132 + vl * 4);
        const float4* rt4 = (const float4*)(sRT + bl * 60);   // 15 float4
        float w0 = sW[vl * NJ + 0], w1 = sW[vl * NJ + 1], w2 = sW[vl * NJ + 2];
        float w3 = sW[vl * NJ + 3], w4 = sW[vl * NJ + 4];
        float4 T4[3];
#pragma unroll
        for (int q = 0; q < 3; q++) {
            float4 r0 = rt4[q], r1 = rt4[3 + q], r2 = rt4[6 + q];
            float4 r3 = rt4[9 + q], r4 = rt4[12 + q];
            T4[q].x = fmaf(w0, r0.x, fmaf(w1, r1.x, fmaf(w2, r2.x, fmaf(w3, r3.x, w4 * r4.x))));
            T4[q].y = fmaf(w0, r0.y, fmaf(w1, r1.y, fmaf(w2, r2.y, fmaf(w3, r3.y, w4 * r4.y))));
            T4[q].z = fmaf(w0, r0.z, fmaf(w1, r1.z, fmaf(w2, r2.z, fmaf(w3, r3.z, w4 * r4.z))));
            T4[q].w = fmaf(w0, r0.w, fmaf(w1, r1.w, fmaf(w2, r2.w, fmaf(w3, r3.w, w4 * r4.w))));
        }
        float px = cv.x + sVT[vl * 3 + 0];
        float py = cv.y + sVT[vl * 3 + 1];
        float pz = cv.z + sVT[vl * 3 + 2];
        float ox = fmaf(T4[0].x, px, fmaf(T4[0].y, py, fmaf(T4[0].z, pz, T4[0].w)));
        float oy = fmaf(T4[1].x, px, fmaf(T4[1].y, py, fmaf(T4[1].z, pz, T4[1].w)));
        float oz = fmaf(T4[2].x, px, fmaf(T4[2].y, py, fmaf(T4[2].z, pz, T4[2].w)));
        if (v < VNUM) {
            size_t base = ((size_t)(b0 + bl) * VNUM + v) * 3;
            out[base + 0] = ox; out[base + 1] = oy; out[base + 2] = oz;
        }
    }
}

// ============================================================
// Launch 5 — kernD: landmark gather
// ============================================================
__global__ void kernD(const int* __restrict__ land, const float* __restrict__ verts,
                      float* __restrict__ lmk)
{
    int i = blockIdx.x * blockDim.x + threadIdx.x;
    if (i >= NB * NLMK) return;
    int b = i / NLMK, k = i % NLMK;
    int v = land[k];
    size_t src = ((size_t)b * VNUM + v) * 3;
    size_t dst = (size_t)i * 3;
    lmk[dst + 0] = verts[src + 0];
    lmk[dst + 1] = verts[src + 1];
    lmk[dst + 2] = verts[src + 2];
}

// ============================================================
extern "C" void kernel_launch(void* const* d_in, const int* in_sizes, int n_in,
                              void* d_out, int out_size)
{
    const float* shape = (const float*)d_in[0];
    const float* expr  = (const float*)d_in[1];
    const float* pose  = (const float*)d_in[2];
    const int*   land  = (const int*)  d_in[3];
    const float* vt    = (const float*)d_in[4];
    const float* sd    = (const float*)d_in[5];
    const float* pd    = (const float*)d_in[6];
    const float* Jreg  = (const float*)d_in[7];
    const float* lw    = (const float*)d_in[8];
    const float* eye   = (const float*)d_in[9];
    const float* neck  = (const float*)d_in[10];
    float* out = (float*)d_out;

    cudaFuncSetAttribute(kernG, cudaFuncAttributeMaxDynamicSharedMemorySize, SM_TOT);
    cudaFuncSetAttribute(kernB, cudaFuncAttributeMaxDynamicSharedMemorySize, KB_SMEM);

    kernPB4<<<NPAD4, KP>>>(sd, pd);                       // launch 1 (also zeroes g_Jr)
    kernA<<<NCHUNK, 256>>>(sd, vt, Jreg);                 // launch 2 (atomics into g_Jr)
    kernB<<<NB / 128, 128, KB_SMEM>>>(shape, expr, pose, eye, neck);  // launch 3
    dim3 gg(NPAD4 / 128, NB / 128);
    kernG<<<gg, 256, SM_TOT>>>(vt, lw, out);              // launch 4  <- profiled
    float* lmk = out + (size_t)NB * VNUM * 3;
    kernD<<<(NB * NLMK + 255) / 256, 256>>>(land, out, lmk);          // launch 5
}

// round 6
// speedup vs baseline: 3.0591x; 1.1807x over previous
#include <cuda_runtime.h>
#include <cuda_bf16.h>
#include <math.h>
#include <stdint.h>

#define VNUM   5023
#define NJ     5
#define NB     1024
#define NSHAPE 100
#define NEXPR  50
#define NBETA  150
#define NLMK   68
#define NPOSE  36
#define JR_COLS 453
#define PD_N   (VNUM * 3)      // 15069

#define KP    192              // padded K: 150 betas + 36 pose feats + 6 zero
#define NPAD4 20096            // 157 * 128 >= 4*VNUM

#define VB      40             // vertices per F1 block
#define F1_BLK  126            // 126*40 = 5040 >= 5024

// ---- device scratch ----
__device__ float g_partial[F1_BLK * NJ * JR_COLS];    // 1.1 MB
__device__ float g_Jr[NJ * JR_COLS];
__device__ float g_relT[NB * NJ * 12];
__device__ __nv_bfloat16 g_A[NB * KP];                // 0.4 MB
__device__ __nv_bfloat16 g_B4[(size_t)NPAD4 * KP];    // 7.7 MB

__device__ __forceinline__ uint32_t smem_u32(const void* p) {
    uint32_t a;
    asm("{ .reg .u64 t; cvta.to.shared.u64 t, %1; cvt.u32.u64 %0, t; }" : "=r"(a) : "l"(p));
    return a;
}

#define LDSM4(R0, R1, R2, R3, ADDR) \
    asm volatile("ldmatrix.sync.aligned.m8n8.x4.shared.b16 {%0,%1,%2,%3}, [%4];" \
        : "=r"(R0), "=r"(R1), "=r"(R2), "=r"(R3) : "r"(ADDR))

#define MMA16816(C, A0, A1, A2, A3, B0, B1) \
    asm volatile("mma.sync.aligned.m16n8k16.row.col.f32.bf16.bf16.f32 " \
        "{%0,%1,%2,%3},{%4,%5,%6,%7},{%8,%9},{%0,%1,%2,%3};" \
        : "+f"((C)[0]), "+f"((C)[1]), "+f"((C)[2]), "+f"((C)[3]) \
        : "r"(A0), "r"(A1), "r"(A2), "r"(A3), "r"(B0), "r"(B1))

#define CP_ASYNC16(DST, SRC) \
    asm volatile("cp.async.cg.shared.global [%0], [%1], 16;" :: "r"(DST), "l"(SRC))
#define CP_ASYNC_WAIT() \
    asm volatile("cp.async.commit_group;\n\tcp.async.wait_group 0;" ::: "memory")

// ============================================================
// Launch 1 — kernF1: fused B4 build + Jr partials.
// 126 blocks x 256 threads; each block owns 40 vertices, processed
// in 5 sub-chunks of 8 (sd rows staged in smem once, used twice).
// ============================================================
__global__ void __launch_bounds__(256) kernF1(
    const float* __restrict__ sd, const float* __restrict__ vt,
    const float* __restrict__ pd, const float* __restrict__ Jreg)
{
    __shared__ float s_sd[8][456];     // 8 rows x (450 sd | 3 vt | pad)
    __shared__ float s_jr[NJ][VB];
    int tid = threadIdx.x;
    int v0 = blockIdx.x * VB;

    for (int i = tid; i < NJ * VB; i += 256) {
        int j = i / VB, vv = i % VB;
        int v = v0 + vv;
        s_jr[j][vv] = (v < VNUM) ? Jreg[j * VNUM + v] : 0.f;
    }

    float acc[10];
#pragma unroll
    for (int q = 0; q < 10; q++) acc[q] = 0.f;
    int col0 = tid, col1 = tid + 256;

    for (int sub = 0; sub < 5; sub++) {
        __syncthreads();
        int vbase = v0 + sub * 8;
        // stage 8 sd rows (+vt) coalesced
        for (int i = tid; i < 8 * 456; i += 256) {
            int r = i / 456, c = i - r * 456;
            int v = vbase + r;
            float val = 0.f;
            if (v < VNUM) {
                if (c < 450)      val = sd[v * 450 + c];
                else if (c < 453) val = vt[v * 3 + (c - 450)];
            }
            s_sd[r][c] = val;
        }
        __syncthreads();

        // Jr partial accumulation
#pragma unroll
        for (int r = 0; r < 8; r++) {
            int vv = sub * 8 + r;
            float j0 = s_jr[0][vv], j1 = s_jr[1][vv], j2 = s_jr[2][vv];
            float j3 = s_jr[3][vv], j4 = s_jr[4][vv];
            float x0 = s_sd[r][col0];
            acc[0] = fmaf(j0, x0, acc[0]); acc[1] = fmaf(j1, x0, acc[1]);
            acc[2] = fmaf(j2, x0, acc[2]); acc[3] = fmaf(j3, x0, acc[3]);
            acc[4] = fmaf(j4, x0, acc[4]);
            if (col1 < JR_COLS) {
                float x1 = s_sd[r][col1];
                acc[5] = fmaf(j0, x1, acc[5]); acc[6] = fmaf(j1, x1, acc[6]);
                acc[7] = fmaf(j2, x1, acc[7]); acc[8] = fmaf(j3, x1, acc[8]);
                acc[9] = fmaf(j4, x1, acc[9]);
            }
        }

        // B4 rows for these 8 vertices (32 rows x 192)
        for (int i = tid; i < 32 * KP; i += 256) {
            int nl = i / KP, k = i - nl * KP;
            int vl2 = nl >> 2, c = nl & 3;
            int v = vbase + vl2;
            int n = v * 4 + c;
            if (n < NPAD4) {
                float val = 0.f;
                if (v < VNUM && c < 3) {
                    if (k < NBETA)              val = s_sd[vl2][c * NBETA + k];
                    else if (k < NBETA + NPOSE) val = pd[(size_t)(k - NBETA) * PD_N + (v * 3 + c)];
                }
                g_B4[(size_t)n * KP + k] = __float2bfloat16(val);
            }
        }
    }

#pragma unroll
    for (int j = 0; j < NJ; j++) {
        g_partial[(blockIdx.x * NJ + j) * JR_COLS + col0] = acc[j];
        if (col1 < JR_COLS)
            g_partial[(blockIdx.x * NJ + j) * JR_COLS + col1] = acc[5 + j];
    }
}

// ============================================================
// Launch 2 — kernA2: reduce 126 partials -> g_Jr.  grid (5,4) x 128
// ============================================================
__global__ void kernA2()
{
    int j = blockIdx.x;
    int col = blockIdx.y * 128 + threadIdx.x;
    if (col >= JR_COLS) return;
    float s = 0.f;
#pragma unroll 6
    for (int ch = 0; ch < F1_BLK; ch++)
        s += g_partial[(ch * NJ + j) * JR_COLS + col];
    g_Jr[j * JR_COLS + col] = s;
}

// ============================================================
// Launch 3 — kernB: joints, Rodrigues, chain -> g_relT + bf16 A rows.
// 32 blocks x 32 threads (1 batch/thread).
// ============================================================
#define BP 153

__global__ void __launch_bounds__(32) kernB(
    const float* __restrict__ shape, const float* __restrict__ expr,
    const float* __restrict__ pose, const float* __restrict__ eye,
    const float* __restrict__ neck)
{
    __shared__ float s_jr[NJ * JR_COLS];
    __shared__ float s_beta[32 * BP];
    int tid = threadIdx.x;
    int b0 = blockIdx.x * 32;

    for (int i = tid; i < NJ * JR_COLS; i += 32) s_jr[i] = g_Jr[i];
    for (int i = tid; i < 32 * NSHAPE; i += 32)
        s_beta[(i / NSHAPE) * BP + (i % NSHAPE)] = shape[b0 * NSHAPE + i];
    for (int i = tid; i < 32 * NEXPR; i += 32)
        s_beta[(i / NEXPR) * BP + NSHAPE + (i % NEXPR)] = expr[b0 * NEXPR + i];
    __syncthreads();

    int b = b0 + tid;
    const float* myb = s_beta + tid * BP;

    float J[NJ][3];
#pragma unroll
    for (int j = 0; j < NJ; j++)
#pragma unroll
        for (int c = 0; c < 3; c++) J[j][c] = s_jr[j * JR_COLS + 450 + c];

    for (int l = 0; l < NBETA; l++) {
        float blv = myb[l];
#pragma unroll
        for (int j = 0; j < NJ; j++)
#pragma unroll
            for (int c = 0; c < 3; c++) J[j][c] = fmaf(s_jr[j * JR_COLS + l], blv, J[j][c]);
    }

    float fp[15];
    fp[0] = pose[b * 6 + 0]; fp[1] = pose[b * 6 + 1]; fp[2] = pose[b * 6 + 2];
    fp[3] = neck[0]; fp[4] = neck[1]; fp[5] = neck[2];
    fp[6] = pose[b * 6 + 3]; fp[7] = pose[b * 6 + 4]; fp[8] = pose[b * 6 + 5];
#pragma unroll
    for (int k = 0; k < 6; k++) fp[9 + k] = eye[k];

    float R[NJ][9];
#pragma unroll
    for (int j = 0; j < NJ; j++) {
        float x = fp[j * 3 + 0], y = fp[j * 3 + 1], z = fp[j * 3 + 2];
        float xa = x + 1e-8f, ya = y + 1e-8f, za = z + 1e-8f;
        float ang = sqrtf(xa * xa + ya * ya + za * za);
        float inv = 1.f / ang;
        float rx = x * inv, ry = y * inv, rz = z * inv;
        float s, c;
        sincosf(ang, &s, &c);
        float t = 1.f - c;
        R[j][0] = 1.f - t * (ry * ry + rz * rz);
        R[j][1] = -s * rz + t * rx * ry;
        R[j][2] =  s * ry + t * rx * rz;
        R[j][3] =  s * rz + t * rx * ry;
        R[j][4] = 1.f - t * (rx * rx + rz * rz);
        R[j][5] = -s * rx + t * ry * rz;
        R[j][6] = -s * ry + t * rx * rz;
        R[j][7] =  s * rx + t * ry * rz;
        R[j][8] = 1.f - t * (rx * rx + ry * ry);
    }

    // --- g_A row: [betas(150) | pose_feature(36) | 0 pad(6)] bf16 ---
    {
        __nv_bfloat16* arow = g_A + (size_t)b * KP;
#pragma unroll 2
        for (int l = 0; l < NBETA; l++) arow[l] = __float2bfloat16(myb[l]);
#pragma unroll
        for (int j = 1; j < NJ; j++)
#pragma unroll
            for (int k = 0; k < 9; k++) {
                float d = (k == 0 || k == 4 || k == 8) ? 1.f : 0.f;
                arow[NBETA + (j - 1) * 9 + k] = __float2bfloat16(R[j][k] - d);
            }
#pragma unroll
        for (int k = NBETA + NPOSE; k < KP; k++) arow[k] = __float2bfloat16(0.f);
    }

    const int par[NJ] = { -1, 0, 1, 1, 1 };
    float rel[NJ][3];
#pragma unroll
    for (int c = 0; c < 3; c++) rel[0][c] = J[0][c];
#pragma unroll
    for (int j = 1; j < NJ; j++)
#pragma unroll
        for (int c = 0; c < 3; c++) rel[j][c] = J[j][c] - J[par[j]][c];

    float cR[NJ][9], ct[NJ][3];
#pragma unroll
    for (int k = 0; k < 9; k++) cR[0][k] = R[0][k];
#pragma unroll
    for (int c = 0; c < 3; c++) ct[0][c] = rel[0][c];
#pragma unroll
    for (int j = 1; j < NJ; j++) {
        int p = par[j];
#pragma unroll
        for (int r = 0; r < 3; r++) {
#pragma unroll
            for (int c = 0; c < 3; c++)
                cR[j][r * 3 + c] = cR[p][r * 3 + 0] * R[j][0 + c]
                                 + cR[p][r * 3 + 1] * R[j][3 + c]
                                 + cR[p][r * 3 + 2] * R[j][6 + c];
            ct[j][r] = cR[p][r * 3 + 0] * rel[j][0] + cR[p][r * 3 + 1] * rel[j][1]
                     + cR[p][r * 3 + 2] * rel[j][2] + ct[p][r];
        }
    }

#pragma unroll
    for (int j = 0; j < NJ; j++)
#pragma unroll
        for (int r = 0; r < 3; r++) {
            float tr = ct[j][r] - (cR[j][r * 3 + 0] * J[j][0] + cR[j][r * 3 + 1] * J[j][1]
                                 + cR[j][r * 3 + 2] * J[j][2]);
            g_relT[b * 60 + j * 12 + r * 4 + 0] = cR[j][r * 3 + 0];
            g_relT[b * 60 + j * 12 + r * 4 + 1] = cR[j][r * 3 + 1];
            g_relT[b * 60 + j * 12 + r * 4 + 2] = cR[j][r * 3 + 2];
            g_relT[b * 60 + j * 12 + r * 4 + 3] = tr;
        }
}

// ============================================================
// Launch 4 — kernG: C[128b x 64n] = A @ B4^T (mma.sync bf16)
// + fused LBS epilogue.  256 thr = 8 warps (4b x 2n), warp tile 32x32.
// K=192 smem-resident, cp.async, 3 CTAs/SM (3 x 76.8 KB).
// smem mainloop: A@0 (128x400B=51200), B@51200 (64x400B=25600) -> 76800
// epilogue reuse: sC@0 (128x68 f32=34816), relT@34816 (30720),
//                 w@65536 (320), vt@65856 (192)
// ============================================================
#define SMB_OFF 51200
#define SM_TOT  76800

__global__ void __launch_bounds__(256, 3) kernG(
    const float* __restrict__ vt, const float* __restrict__ lw,
    float* __restrict__ out)
{
    extern __shared__ char smr[];
    uint32_t sb = smem_u32(smr);
    int tid = threadIdx.x;
    int lane = tid & 31, w = tid >> 5;
    int wm = w & 3, wn = w >> 2;          // 4b x 2n grid, warp tile 32b x 32n
    int n0 = blockIdx.x * 64;
    int b0 = blockIdx.y * 128;
    int v0 = n0 >> 2;                     // 16 vertices per tile

    // --- stage A (128x24 uint4) + B (64x24 uint4) via cp.async, pitch 400B ---
    {
        const uint4* gA4 = (const uint4*)(g_A + (size_t)b0 * KP);
        const uint4* gB4 = (const uint4*)(g_B4 + (size_t)n0 * KP);
        for (int i = tid; i < 128 * 24; i += 256) {
            int row = i / 24, q = i - row * 24;
            CP_ASYNC16(sb + row * 400 + q * 16, gA4 + i);
        }
        for (int i = tid; i < 64 * 24; i += 256) {
            int row = i / 24, q = i - row * 24;
            CP_ASYNC16(sb + SMB_OFF + row * 400 + q * 16, gB4 + i);
        }
        CP_ASYNC_WAIT();
    }
    __syncthreads();

    float acc[2][4][4];
#pragma unroll
    for (int a = 0; a < 2; a++)
#pragma unroll
        for (int j = 0; j < 4; j++)
#pragma unroll
            for (int k = 0; k < 4; k++) acc[a][j][k] = 0.f;

    int lrow = lane & 15;
    uint32_t koff = (uint32_t)((lane >> 4) * 16);
    uint32_t aBase = sb + (wm * 32 + lrow) * 400 + koff;
    uint32_t bBase = sb + SMB_OFF + (wn * 32 + lrow) * 400 + koff;

#pragma unroll
    for (int ks = 0; ks < 12; ks++) {
        uint32_t kb = (uint32_t)ks * 32u;
        uint32_t ra[2][4], rb[2][4];
        LDSM4(ra[0][0], ra[0][1], ra[0][2], ra[0][3], aBase + kb);
        LDSM4(ra[1][0], ra[1][1], ra[1][2], ra[1][3], aBase + 16 * 400 + kb);
        LDSM4(rb[0][0], rb[0][1], rb[0][2], rb[0][3], bBase + kb);
        LDSM4(rb[1][0], rb[1][1], rb[1][2], rb[1][3], bBase + 16 * 400 + kb);
#pragma unroll
        for (int a = 0; a < 2; a++)
#pragma unroll
            for (int jj = 0; jj < 2; jj++) {
                MMA16816(acc[a][jj * 2],     ra[a][0], ra[a][1], ra[a][2], ra[a][3],
                         rb[jj][0], rb[jj][2]);
                MMA16816(acc[a][jj * 2 + 1], ra[a][0], ra[a][1], ra[a][2], ra[a][3],
                         rb[jj][1], rb[jj][3]);
            }
    }

    __syncthreads();   // done reading A/B smem

    // --- write accumulators to sC [128 x 68] f32 ---
    float* sC = (float*)smr;
#pragma unroll
    for (int a = 0; a < 2; a++) {
        int r = wm * 32 + a * 16 + (lane >> 2);
        int cb = wn * 32 + (lane & 3) * 2;
#pragma unroll
        for (int j = 0; j < 4; j++) {
            int c = cb + j * 8;
            sC[r * 68 + c]           = acc[a][j][0];
            sC[r * 68 + c + 1]       = acc[a][j][1];
            sC[(r + 8) * 68 + c]     = acc[a][j][2];
            sC[(r + 8) * 68 + c + 1] = acc[a][j][3];
        }
    }

    // --- stage relT / weights / template ---
    float* sRT = (float*)(smr + 34816);
    for (int i = tid; i < 128 * 60; i += 256) sRT[i] = g_relT[b0 * 60 + i];
    float* sW = (float*)(smr + 65536);
    if (tid < 16 * NJ) {
        int vl = tid / NJ;
        int v = v0 + vl;
        sW[tid] = (v < VNUM) ? lw[v * NJ + (tid % NJ)] : 0.f;
    }
    float* sVT = (float*)(smr + 65856);
    if (tid < 48) {
        int vl = tid / 3;
        int v = v0 + vl;
        sVT[tid] = (v < VNUM) ? vt[v * 3 + (tid % 3)] : 0.f;
    }
    __syncthreads();

    // --- per (b, v): blend transform (float4 vectorized), apply, store ---
#pragma unroll 4
    for (int it = 0; it < 8; it++) {
        int p = it * 256 + tid;
        int vl = p & 15, bl = p >> 4;
        int v = v0 + vl;
        float4 cv = *(const float4*)(sC + bl * 68 + vl * 4);
        const float4* rt4 = (const float4*)(sRT + bl * 60);   // 15 float4
        float w0 = sW[vl * NJ + 0], w1 = sW[vl * NJ + 1], w2 = sW[vl * NJ + 2];
        float w3 = sW[vl * NJ + 3], w4 = sW[vl * NJ + 4];
        float4 T4[3];
#pragma unroll
        for (int q = 0; q < 3; q++) {
            float4 r0 = rt4[q], r1 = rt4[3 + q], r2 = rt4[6 + q];
            float4 r3 = rt4[9 + q], r4 = rt4[12 + q];
            T4[q].x = fmaf(w0, r0.x, fmaf(w1, r1.x, fmaf(w2, r2.x, fmaf(w3, r3.x, w4 * r4.x))));
            T4[q].y = fmaf(w0, r0.y, fmaf(w1, r1.y, fmaf(w2, r2.y, fmaf(w3, r3.y, w4 * r4.y))));
            T4[q].z = fmaf(w0, r0.z, fmaf(w1, r1.z, fmaf(w2, r2.z, fmaf(w3, r3.z, w4 * r4.z))));
            T4[q].w = fmaf(w0, r0.w, fmaf(w1, r1.w, fmaf(w2, r2.w, fmaf(w3, r3.w, w4 * r4.w))));
        }
        float px = cv.x + sVT[vl * 3 + 0];
        float py = cv.y + sVT[vl * 3 + 1];
        float pz = cv.z + sVT[vl * 3 + 2];
        float ox = fmaf(T4[0].x, px, fmaf(T4[0].y, py, fmaf(T4[0].z, pz, T4[0].w)));
        float oy = fmaf(T4[1].x, px, fmaf(T4[1].y, py, fmaf(T4[1].z, pz, T4[1].w)));
        float oz = fmaf(T4[2].x, px, fmaf(T4[2].y, py, fmaf(T4[2].z, pz, T4[2].w)));
        if (v < VNUM) {
            size_t base = ((size_t)(b0 + bl) * VNUM + v) * 3;
            out[base + 0] = ox; out[base + 1] = oy; out[base + 2] = oz;
        }
    }
}

// ============================================================
// Launch 5 — kernD: landmark gather
// ============================================================
__global__ void kernD(const int* __restrict__ land, const float* __restrict__ verts,
                      float* __restrict__ lmk)
{
    int i = blockIdx.x * blockDim.x + threadIdx.x;
    if (i >= NB * NLMK) return;
    int b = i / NLMK, k = i % NLMK;
    int v = land[k];
    size_t src = ((size_t)b * VNUM + v) * 3;
    size_t dst = (size_t)i * 3;
    lmk[dst + 0] = verts[src + 0];
    lmk[dst + 1] = verts[src + 1];
    lmk[dst + 2] = verts[src + 2];
}

// ============================================================
extern "C" void kernel_launch(void* const* d_in, const int* in_sizes, int n_in,
                              void* d_out, int out_size)
{
    const float* shape = (const float*)d_in[0];
    const float* expr  = (const float*)d_in[1];
    const float* pose  = (const float*)d_in[2];
    const int*   land  = (const int*)  d_in[3];
    const float* vt    = (const float*)d_in[4];
    const float* sd    = (const float*)d_in[5];
    const float* pd    = (const float*)d_in[6];
    const float* Jreg  = (const float*)d_in[7];
    const float* lw    = (const float*)d_in[8];
    const float* eye   = (const float*)d_in[9];
    const float* neck  = (const float*)d_in[10];
    float* out = (float*)d_out;

    cudaFuncSetAttribute(kernG, cudaFuncAttributeMaxDynamicSharedMemorySize, SM_TOT);

    kernF1<<<F1_BLK, 256>>>(sd, vt, pd, Jreg);            // launch 1
    dim3 ga(NJ, 4);
    kernA2<<<ga, 128>>>();                                // launch 2
    kernB<<<NB / 32, 32>>>(shape, expr, pose, eye, neck); // launch 3
    dim3 gg(NPAD4 / 64, NB / 128);
    kernG<<<gg, 256, SM_TOT>>>(vt, lw, out);              // launch 4  <- profiled
    float* lmk = out + (size_t)NB * VNUM * 3;
    kernD<<<(NB * NLMK + 255) / 256, 256>>>(land, out, lmk);  // launch 5
}